// round 11
// baseline (speedup 1.0000x reference)
#include <cuda_runtime.h>
#include <cuda_fp16.h>
#include <math.h>
#include <stdint.h>

#define NB   16384
#define HH   512
#define NOUT 4
#define NFF  2048
#define NHOR 5
#define GRID_P 296               // 2 CTAs/SM x 148 SMs

// ---------------- fp32 scratch ----------------------------------------------
__device__ float g_gh[(size_t)NB * 3 * HH];       // gate pre-activations [B,3H]
__device__ float g_xy[(size_t)NB * NOUT];         // running xy
__device__ float g_part[(size_t)NB * 16 * NOUT];  // mlp partials [B,16,4]

// ---------------- fp16 hi/lo planes (GEMM operands) -------------------------
__device__ __align__(16) __half g_hp_h[(size_t)NB * HH];      // hprev (hx)
__device__ __align__(16) __half g_hp_l[(size_t)NB * HH];
__device__ __align__(16) __half g_hc_h[(size_t)NB * 2 * HH];  // hcat [h1|h2]
__device__ __align__(16) __half g_hc_l[(size_t)NB * 2 * HH];
__device__ __align__(16) __half g_hr_h[(size_t)NB * HH];      // relu(hx)
__device__ __align__(16) __half g_hr_l[(size_t)NB * HH];
__device__ __align__(16) __half g_whh_h[3 * HH * HH];
__device__ __align__(16) __half g_whh_l[3 * HH * HH];
__device__ __align__(16) __half g_wfc_h[HH * 2 * HH];
__device__ __align__(16) __half g_wfc_l[HH * 2 * HH];
__device__ __align__(16) __half g_w1_h[NFF * HH];
__device__ __align__(16) __half g_w1_l[NFF * HH];

// ---------------- helpers ---------------------------------------------------
__device__ __forceinline__ uint32_t smem_u32(const void* p) {
    uint32_t a;
    asm("{ .reg .u64 t; cvta.to.shared.u64 t, %1; cvt.u32.u64 %0, t; }"
        : "=r"(a) : "l"(p));
    return a;
}
__device__ __forceinline__ void split1(float x, __half& h, __half& l) {
    h = __float2half_rn(x);
    l = __float2half_rn(x - __half2float(h));
}
__device__ __forceinline__ void ldsm4(uint32_t& r0, uint32_t& r1,
                                      uint32_t& r2, uint32_t& r3, uint32_t addr) {
    asm volatile("ldmatrix.sync.aligned.m8n8.x4.shared.b16 {%0,%1,%2,%3}, [%4];"
                 : "=r"(r0), "=r"(r1), "=r"(r2), "=r"(r3) : "r"(addr));
}
__device__ __forceinline__ void hmma(float* d, const uint32_t* a,
                                     uint32_t b0, uint32_t b1) {
    asm volatile(
        "mma.sync.aligned.m16n8k16.row.col.f32.f16.f16.f32 "
        "{%0,%1,%2,%3}, {%4,%5,%6,%7}, {%8,%9}, {%0,%1,%2,%3};"
        : "+f"(d[0]), "+f"(d[1]), "+f"(d[2]), "+f"(d[3])
        : "r"(a[0]), "r"(a[1]), "r"(a[2]), "r"(a[3]), "r"(b0), "r"(b1));
}
__device__ __forceinline__ void cpasync16(uint32_t dst, const void* src) {
    asm volatile("cp.async.cg.shared.global [%0], [%1], 16;" :: "r"(dst), "l"(src));
}

// smem plane: 128 rows x 32 fp16 = 64B/row; XOR swizzle keeps LDGSTS stores and
// ldmatrix reads conflict-free without padding.
#define STAGES  3
#define PL      8192            // one plane: 128*64B
#define STG     (4 * PL)        // Ah, Al, Wh, Wl
#define SMEM_DYN (STAGES * STG) // 96 KB

__device__ __forceinline__ uint32_t sw_addr(uint32_t base, int row, int cgrp) {
    return base + row * 64 + (uint32_t)((cgrp ^ ((row >> 1) & 3)) << 4);
}

// =====================  persistent split-fp16 HMMA GEMM  ====================
// C[B,N] = A @ W^T + bias; A,W given as fp16 hi/lo planes.
// Persistent: grid=GRID_P CTAs loop over ntiles output tiles (N-major).
// PASSES=3: hh + hl + lh (~fp32). PASSES=2: (hi+lo)*W_hi (~2^-12).
template <int STORE_C, int WSPLITS, int PASSES, int FUSED>
__global__ __launch_bounds__(256, 2)
void hgemm(const __half* __restrict__ Ah, const __half* __restrict__ Al, int lda,
           const __half* __restrict__ Wh, const __half* __restrict__ Wl, int K,
           const float* __restrict__ bias, float* __restrict__ C, int N,
           __half* __restrict__ Oh, __half* __restrict__ Ol,
           __half* __restrict__ Rh, __half* __restrict__ Rl,
           const float* __restrict__ w2g, float* __restrict__ part,
           int ntN, int ntiles)
{
    extern __shared__ char dsm[];
    const uint32_t sb = smem_u32(dsm);

    const int tid  = threadIdx.x;
    const int wid  = tid >> 5;
    const int lane = tid & 31;
    const int wm   = wid & 1;
    const int wn   = wid >> 1;
    const int grp  = lane >> 3;
    const int wi   = lane & 7;

    const int r0c = tid >> 2, cg0 = tid & 3;
    const int r1c = (tid + 256) >> 2, cg1 = tid & 3;

    const int rowA0 = wm * 64 + (grp & 1) * 8 + wi;
    const int sA    = (rowA0 >> 1) & 3;
    const int cA    = grp >> 1;
    const int rowW0 = wn * 32 + (grp >> 1) * 8 + wi;
    const int sW    = (rowW0 >> 1) & 3;
    const int cW    = grp & 1;

    const int nchunk = K >> 5;   // K / 32

    for (int t = blockIdx.x; t < ntiles; t += GRID_P) {
        const int bm = t / ntN;
        const int bn = t - bm * ntN;

        const __half* Abh = Ah + (size_t)bm * 128 * lda;
        const __half* Abl = Al + (size_t)bm * 128 * lda;
        const __half* Wbh = Wh + (size_t)bn * 128 * K;
        const __half* Wbl = Wl + (size_t)bn * 128 * K;

        float acc[4][4][4];
#pragma unroll
        for (int mt = 0; mt < 4; ++mt)
#pragma unroll
            for (int nt = 0; nt < 4; ++nt)
#pragma unroll
                for (int r = 0; r < 4; ++r) acc[mt][nt][r] = 0.f;

#define ISSUE(c) do {                                                          \
    int k0_ = (c) << 5;                                                        \
    uint32_t stg_ = sb + (uint32_t)((c) % STAGES) * STG;                       \
    uint32_t d0_ = sw_addr(stg_, r0c, cg0);                                    \
    cpasync16(d0_,          Abh + (size_t)r0c * lda + k0_ + cg0 * 8);          \
    cpasync16(d0_ + PL,     Abl + (size_t)r0c * lda + k0_ + cg0 * 8);          \
    cpasync16(d0_ + 2*PL,   Wbh + (size_t)r0c * K  + k0_ + cg0 * 8);           \
    if (PASSES == 3)                                                           \
        cpasync16(d0_ + 3*PL, Wbl + (size_t)r0c * K + k0_ + cg0 * 8);          \
    uint32_t d1_ = sw_addr(stg_, r1c, cg1);                                    \
    cpasync16(d1_,          Abh + (size_t)r1c * lda + k0_ + cg1 * 8);          \
    cpasync16(d1_ + PL,     Abl + (size_t)r1c * lda + k0_ + cg1 * 8);          \
    cpasync16(d1_ + 2*PL,   Wbh + (size_t)r1c * K  + k0_ + cg1 * 8);           \
    if (PASSES == 3)                                                           \
        cpasync16(d1_ + 3*PL, Wbl + (size_t)r1c * K + k0_ + cg1 * 8);          \
} while (0)

#pragma unroll
        for (int s = 0; s < STAGES - 1; ++s) {
            ISSUE(s);
            asm volatile("cp.async.commit_group;");
        }

        for (int c = 0; c < nchunk; ++c) {
            asm volatile("cp.async.wait_group %0;" :: "n"(STAGES - 2));
            __syncthreads();
            if (c + STAGES - 1 < nchunk) ISSUE(c + STAGES - 1);
            asm volatile("cp.async.commit_group;");

            const uint32_t stg = sb + (uint32_t)(c % STAGES) * STG;
#pragma unroll
            for (int ks = 0; ks < 2; ++ks) {
                uint32_t bh[4][2], bl[4][2];
#pragma unroll
                for (int nh = 0; nh < 2; ++nh) {
                    uint32_t wd = stg + 2 * PL + (uint32_t)(rowW0 + nh * 16) * 64
                                + (uint32_t)(((ks * 2 + cW) ^ sW) << 4);
                    uint32_t r0, r1, r2, r3;
                    ldsm4(r0, r1, r2, r3, wd);
                    bh[nh * 2 + 0][0] = r0; bh[nh * 2 + 0][1] = r1;
                    bh[nh * 2 + 1][0] = r2; bh[nh * 2 + 1][1] = r3;
                    if (PASSES == 3) {
                        ldsm4(r0, r1, r2, r3, wd + PL);
                        bl[nh * 2 + 0][0] = r0; bl[nh * 2 + 0][1] = r1;
                        bl[nh * 2 + 1][0] = r2; bl[nh * 2 + 1][1] = r3;
                    }
                }
                uint32_t a[4][4];
#pragma unroll
                for (int mt = 0; mt < 4; ++mt) {
                    uint32_t ad = stg + (uint32_t)(rowA0 + mt * 16) * 64
                                + (uint32_t)(((ks * 2 + cA) ^ sA) << 4);
                    ldsm4(a[mt][0], a[mt][1], a[mt][2], a[mt][3], ad);
#pragma unroll
                    for (int nt = 0; nt < 4; ++nt) {
                        hmma(acc[mt][nt], a[mt], bh[nt][0], bh[nt][1]);
                        if (PASSES == 3)
                            hmma(acc[mt][nt], a[mt], bl[nt][0], bl[nt][1]);
                    }
                }
#pragma unroll
                for (int mt = 0; mt < 4; ++mt) {
                    uint32_t ad = stg + PL + (uint32_t)(rowA0 + mt * 16) * 64
                                + (uint32_t)(((ks * 2 + cA) ^ sA) << 4);
                    ldsm4(a[mt][0], a[mt][1], a[mt][2], a[mt][3], ad);
#pragma unroll
                    for (int nt = 0; nt < 4; ++nt)
                        hmma(acc[mt][nt], a[mt], bh[nt][0], bh[nt][1]);
                }
            }
        }
#undef ISSUE

        if (FUSED) {
            // ---- fused mlp2: relu(tile) . w2 -> partials [B, 16, 4] --------
            __syncthreads();                   // pipeline smem now reusable
            float* w2s = (float*)dsm;          // [4][128]
            float* red = (float*)(dsm + 2048); // [4 warps-n][128 rows][4 outs]
            if (tid < 128) {
#pragma unroll
                for (int o = 0; o < 4; ++o)
                    w2s[o * 128 + tid] = w2g[(size_t)o * NFF + bn * 128 + tid];
            }
            __syncthreads();

            float po[8][4];
#pragma unroll
            for (int i = 0; i < 8; ++i)
#pragma unroll
                for (int o = 0; o < 4; ++o) po[i][o] = 0.f;

#pragma unroll
            for (int mt = 0; mt < 4; ++mt) {
#pragma unroll
                for (int nt = 0; nt < 4; ++nt) {
                    const int clb = wn * 32 + (lane & 3) * 2 + nt * 8;
                    const float b0 = bias[bn * 128 + clb];
                    const float b1v = bias[bn * 128 + clb + 1];
                    float t00 = fmaxf(acc[mt][nt][0] + b0, 0.f);
                    float t01 = fmaxf(acc[mt][nt][1] + b1v, 0.f);
                    float t10 = fmaxf(acc[mt][nt][2] + b0, 0.f);
                    float t11 = fmaxf(acc[mt][nt][3] + b1v, 0.f);
#pragma unroll
                    for (int o = 0; o < 4; ++o) {
                        float w0 = w2s[o * 128 + clb], w1w = w2s[o * 128 + clb + 1];
                        po[mt * 2 + 0][o] += t00 * w0 + t01 * w1w;
                        po[mt * 2 + 1][o] += t10 * w0 + t11 * w1w;
                    }
                }
            }
#pragma unroll
            for (int off = 1; off <= 2; off <<= 1)
#pragma unroll
                for (int i = 0; i < 8; ++i)
#pragma unroll
                    for (int o = 0; o < 4; ++o)
                        po[i][o] += __shfl_xor_sync(0xffffffffu, po[i][o], off);

            if ((lane & 3) == 0) {
                const int rq = lane >> 2;
#pragma unroll
                for (int i = 0; i < 8; ++i) {
                    int row = wm * 64 + rq + (i >> 1) * 16 + (i & 1) * 8;
#pragma unroll
                    for (int o = 0; o < 4; ++o)
                        red[(wn * 128 + row) * 4 + o] = po[i][o];
                }
            }
            __syncthreads();
            if (tid < 128) {
                float4 s = make_float4(0.f, 0.f, 0.f, 0.f);
#pragma unroll
                for (int w = 0; w < 4; ++w) {
                    float4 v = *(float4*)&red[(w * 128 + tid) * 4];
                    s.x += v.x; s.y += v.y; s.z += v.z; s.w += v.w;
                }
                *(float4*)(part + ((size_t)(bm * 128 + tid) * 16 + bn) * 4) = s;
            }
            __syncthreads();   // protect smem from next tile's cp.async
            continue;
        }

        // ---- standard epilogue ---------------------------------------------
        const int row0 = bm * 128 + wm * 64 + (lane >> 2);
        const int col0 = bn * 128 + wn * 32 + (lane & 3) * 2;
#pragma unroll
        for (int mt = 0; mt < 4; ++mt) {
#pragma unroll
            for (int nt = 0; nt < 4; ++nt) {
                const int cI = col0 + nt * 8;
                const float b0 = bias[cI], b1 = bias[cI + 1];
                float2 v0, v1;
                v0.x = acc[mt][nt][0] + b0; v0.y = acc[mt][nt][1] + b1;
                v1.x = acc[mt][nt][2] + b0; v1.y = acc[mt][nt][3] + b1;
                const int r = row0 + mt * 16;
                if (STORE_C) {
                    *(float2*)(C + (size_t)r * N + cI)       = v0;
                    *(float2*)(C + (size_t)(r + 8) * N + cI) = v1;
                }
                if (WSPLITS) {
                    __half h0, l0, h1, l1;
                    split1(v0.x, h0, l0); split1(v0.y, h1, l1);
                    *(__half2*)(Oh + (size_t)r * N + cI) = __halves2half2(h0, h1);
                    *(__half2*)(Ol + (size_t)r * N + cI) = __halves2half2(l0, l1);
                    split1(v1.x, h0, l0); split1(v1.y, h1, l1);
                    *(__half2*)(Oh + (size_t)(r + 8) * N + cI) = __halves2half2(h0, h1);
                    *(__half2*)(Ol + (size_t)(r + 8) * N + cI) = __halves2half2(l0, l1);
                    float r0x = fmaxf(v0.x, 0.f), r0y = fmaxf(v0.y, 0.f);
                    float r1x = fmaxf(v1.x, 0.f), r1y = fmaxf(v1.y, 0.f);
                    split1(r0x, h0, l0); split1(r0y, h1, l1);
                    *(__half2*)(Rh + (size_t)r * N + cI) = __halves2half2(h0, h1);
                    *(__half2*)(Rl + (size_t)r * N + cI) = __halves2half2(l0, l1);
                    split1(r1x, h0, l0); split1(r1y, h1, l1);
                    *(__half2*)(Rh + (size_t)(r + 8) * N + cI) = __halves2half2(h0, h1);
                    *(__half2*)(Rl + (size_t)(r + 8) * N + cI) = __halves2half2(l0, l1);
                }
            }
        }
    }
}

// ---------------- prep: all weight/state splits + xy zero, ONE launch -------
__global__ void prep_kernel(const float* __restrict__ whh, const float* __restrict__ wfc,
                            const float* __restrict__ w1f, const float* __restrict__ ptf,
                            __half* __restrict__ whh_h, __half* __restrict__ whh_l,
                            __half* __restrict__ wfc_h, __half* __restrict__ wfc_l,
                            __half* __restrict__ w1_h,  __half* __restrict__ w1_l,
                            __half* __restrict__ hp_h,  __half* __restrict__ hp_l,
                            float* __restrict__ xy)
{
    const int n0 = 3 * HH * HH;
    const int n1 = n0 + HH * 2 * HH;
    const int n2 = n1 + NFF * HH;
    const int n3 = n2 + NB * HH;
    const int n4 = n3 + NB * NOUT;
    int i = (blockIdx.x * blockDim.x + threadIdx.x) * 4;
    if (i >= n4) return;
    if (i >= n3) {
        *(float4*)(xy + (i - n3)) = make_float4(0.f, 0.f, 0.f, 0.f);
        return;
    }
    const float* src; __half *hi, *lo; int off;
    if (i < n0)      { src = whh; hi = whh_h; lo = whh_l; off = i; }
    else if (i < n1) { src = wfc; hi = wfc_h; lo = wfc_l; off = i - n0; }
    else if (i < n2) { src = w1f; hi = w1_h;  lo = w1_l;  off = i - n1; }
    else             { src = ptf; hi = hp_h;  lo = hp_l;  off = i - n2; }
    float4 v = *(const float4*)(src + off);
    __half h0, l0, h1, l1, h2, l2, h3, l3;
    split1(v.x, h0, l0); split1(v.y, h1, l1);
    split1(v.z, h2, l2); split1(v.w, h3, l3);
    *(__half2*)(hi + off)     = __halves2half2(h0, h1);
    *(__half2*)(hi + off + 2) = __halves2half2(h2, h3);
    *(__half2*)(lo + off)     = __halves2half2(l0, l1);
    *(__half2*)(lo + off + 2) = __halves2half2(l2, l3);
}

// ---------------- GRU gate fusion (r,z,n order); planes in, planes out ------
__global__ void gru_gates_kernel(const float* __restrict__ gh,
                                 const float* __restrict__ x, int ldx,
                                 const __half* __restrict__ php,  // hprev hi
                                 const __half* __restrict__ plp,  // hprev lo
                                 int ldh,
                                 const float* __restrict__ w_ih,  // [3H,4]
                                 const float* __restrict__ b_ih,  // [3H]
                                 __half* __restrict__ ph,         // out hi plane
                                 __half* __restrict__ pl,         // out lo plane
                                 int ldp)
{
    int j = blockIdx.x * blockDim.x + threadIdx.x;   // 0..H-1
    int b = blockIdx.y;
    float4 xv = *(const float4*)(x + (size_t)b * ldx);

    float ig[3];
#pragma unroll
    for (int g = 0; g < 3; ++g) {
        int rI = g * HH + j;
        float4 w = *(const float4*)(w_ih + (size_t)rI * 4);
        ig[g] = b_ih[rI] + xv.x * w.x + xv.y * w.y + xv.z * w.z + xv.w * w.w;
    }
    const float* ghb = gh + (size_t)b * (3 * HH);
    float gr = ghb[j], gz = ghb[HH + j], gn = ghb[2 * HH + j];
    float r = 1.f / (1.f + expf(-(ig[0] + gr)));
    float z = 1.f / (1.f + expf(-(ig[1] + gz)));
    float n = tanhf(ig[2] + r * gn);
    float hp = __half2float(php[(size_t)b * ldh + j])
             + __half2float(plp[(size_t)b * ldh + j]);
    float h = (1.f - z) * n + z * hp;

    __half hh_, hl_;
    split1(h, hh_, hl_);
    ph[(size_t)b * ldp + j] = hh_;
    pl[(size_t)b * ldp + j] = hl_;
}

// ---------------- finalize: sum partials, update xy, write out --------------
__global__ void finalize_kernel(const float* __restrict__ part,
                                const float* __restrict__ b2,
                                float* __restrict__ xy,
                                float* __restrict__ out, int step)
{
    int b = blockIdx.x * blockDim.x + threadIdx.x;
    if (b >= NB) return;
    const float4* p = (const float4*)(part + (size_t)b * 64);
    float4 s = p[0];
#pragma unroll
    for (int j = 1; j < 16; ++j) {
        float4 v = p[j];
        s.x += v.x; s.y += v.y; s.z += v.z; s.w += v.w;
    }
    float4 cur = *(float4*)(xy + (size_t)b * 4);
    cur.x += s.x + b2[0];
    cur.y += s.y + b2[1];
    cur.z += s.z + b2[2];
    cur.w += s.w + b2[3];
    *(float4*)(xy + (size_t)b * 4) = cur;
    *(float4*)(out + (size_t)b * NHOR * NOUT + step * NOUT) = cur;
}

// ---------------- launch -----------------------------------------------------
extern "C" void kernel_launch(void* const* d_in, const int* in_sizes, int n_in,
                              void* d_out, int out_size)
{
    const float* pv   = (const float*)d_in[0];
    const float* ptf  = (const float*)d_in[1];
    const float* w_ih = (const float*)d_in[2];
    const float* w_hh = (const float*)d_in[3];
    const float* b_ih = (const float*)d_in[4];
    const float* b_hh = (const float*)d_in[5];
    const float* w_fc = (const float*)d_in[6];
    const float* b_fc = (const float*)d_in[7];
    const float* w1   = (const float*)d_in[8];
    const float* b1   = (const float*)d_in[9];
    const float* w2   = (const float*)d_in[10];
    const float* b2   = (const float*)d_in[11];
    float* out = (float*)d_out;

    float *gh, *xy, *part;
    __half *hp_h, *hp_l, *hc_h, *hc_l, *hr_h, *hr_l;
    __half *whh_h, *whh_l, *wfc_h, *wfc_l, *w1_h, *w1_l;
    cudaGetSymbolAddress((void**)&gh, g_gh);
    cudaGetSymbolAddress((void**)&xy, g_xy);
    cudaGetSymbolAddress((void**)&part, g_part);
    cudaGetSymbolAddress((void**)&hp_h, g_hp_h);
    cudaGetSymbolAddress((void**)&hp_l, g_hp_l);
    cudaGetSymbolAddress((void**)&hc_h, g_hc_h);
    cudaGetSymbolAddress((void**)&hc_l, g_hc_l);
    cudaGetSymbolAddress((void**)&hr_h, g_hr_h);
    cudaGetSymbolAddress((void**)&hr_l, g_hr_l);
    cudaGetSymbolAddress((void**)&whh_h, g_whh_h);
    cudaGetSymbolAddress((void**)&whh_l, g_whh_l);
    cudaGetSymbolAddress((void**)&wfc_h, g_wfc_h);
    cudaGetSymbolAddress((void**)&wfc_l, g_wfc_l);
    cudaGetSymbolAddress((void**)&w1_h, g_w1_h);
    cudaGetSymbolAddress((void**)&w1_l, g_w1_l);

    cudaFuncSetAttribute(hgemm<1, 0, 3, 0>, cudaFuncAttributeMaxDynamicSharedMemorySize, SMEM_DYN);
    cudaFuncSetAttribute(hgemm<0, 1, 3, 0>, cudaFuncAttributeMaxDynamicSharedMemorySize, SMEM_DYN);
    cudaFuncSetAttribute(hgemm<0, 0, 2, 1>, cudaFuncAttributeMaxDynamicSharedMemorySize, SMEM_DYN);

    // ---- prep (single launch): split weights + ptf, zero xy ----
    {
        const int n4 = 3 * HH * HH + HH * 2 * HH + NFF * HH + NB * HH + NB * NOUT;
        prep_kernel<<<(n4 / 4 + 255) / 256, 256>>>(
            w_hh, w_fc, w1, ptf,
            whh_h, whh_l, wfc_h, wfc_l, w1_h, w1_l, hp_h, hp_l, xy);
    }

    for (int i = 0; i < NHOR; ++i) {
        // cell 1: gh = hprev @ w_hh^T + b_hh ; h1 = gates(xy, gh, hprev)
        hgemm<1, 0, 3, 0><<<GRID_P, 256, SMEM_DYN>>>(
            hp_h, hp_l, HH, whh_h, whh_l, HH, b_hh, gh, 3 * HH,
            nullptr, nullptr, nullptr, nullptr, nullptr, nullptr,
            12, (NB / 128) * 12);
        gru_gates_kernel<<<dim3(HH / 256, NB), 256>>>(
            gh, xy, NOUT, hp_h, hp_l, HH, w_ih, b_ih,
            hc_h, hc_l, 2 * HH);

        // cell 2: gh = h1 @ w_hh^T + b_hh ; h2 = gates(pv_i, gh, h1)
        hgemm<1, 0, 3, 0><<<GRID_P, 256, SMEM_DYN>>>(
            hc_h, hc_l, 2 * HH, whh_h, whh_l, HH, b_hh, gh, 3 * HH,
            nullptr, nullptr, nullptr, nullptr, nullptr, nullptr,
            12, (NB / 128) * 12);
        gru_gates_kernel<<<dim3(HH / 256, NB), 256>>>(
            gh, pv + i * NOUT, NHOR * NOUT, hc_h, hc_l, 2 * HH, w_ih, b_ih,
            hc_h + HH, hc_l + HH, 2 * HH);

        // hx = hcat @ w_fc^T + b_fc ; emit hp planes + relu planes (no fp32 C)
        hgemm<0, 1, 3, 0><<<GRID_P, 256, SMEM_DYN>>>(
            hc_h, hc_l, 2 * HH, wfc_h, wfc_l, 2 * HH, b_fc, nullptr, HH,
            hp_h, hp_l, hr_h, hr_l, nullptr, nullptr,
            4, (NB / 128) * 4);

        // fused: t = relu(relu(hx) @ w1^T + b1); partials = t-tile . w2
        hgemm<0, 0, 2, 1><<<GRID_P, 256, SMEM_DYN>>>(
            hr_h, hr_l, HH, w1_h, w1_l, HH, b1, nullptr, NFF,
            nullptr, nullptr, nullptr, nullptr, w2, part,
            16, (NB / 128) * 16);

        // xy += sum(partials) + b2 ; out[:, i, :] = xy
        finalize_kernel<<<(NB + 255) / 256, 256>>>(part, b2, xy, out, i);
    }
}

// round 12
// speedup vs baseline: 1.0870x; 1.0870x over previous
#include <cuda_runtime.h>
#include <cuda_fp16.h>
#include <math.h>
#include <stdint.h>

#define NB   16384
#define HH   512
#define NOUT 4
#define NFF  2048
#define NHOR 5

// ---------------- fp32 scratch ----------------------------------------------
__device__ float g_gh[(size_t)NB * 3 * HH];       // gate pre-activations [B,3H]
__device__ float g_xy[(size_t)NB * NOUT];         // running xy
__device__ float g_part[(size_t)NB * 16 * NOUT];  // mlp partials [B,16,4]

// ---------------- fp16 hi/lo planes (GEMM operands) -------------------------
__device__ __align__(16) __half g_hp_h[(size_t)NB * HH];      // hprev (hx)
__device__ __align__(16) __half g_hp_l[(size_t)NB * HH];
__device__ __align__(16) __half g_hc_h[(size_t)NB * 2 * HH];  // hcat [h1|h2]
__device__ __align__(16) __half g_hc_l[(size_t)NB * 2 * HH];
__device__ __align__(16) __half g_hr_h[(size_t)NB * HH];      // relu(hx)
__device__ __align__(16) __half g_hr_l[(size_t)NB * HH];
__device__ __align__(16) __half g_whh_h[3 * HH * HH];
__device__ __align__(16) __half g_whh_l[3 * HH * HH];
__device__ __align__(16) __half g_wfc_h[HH * 2 * HH];
__device__ __align__(16) __half g_wfc_l[HH * 2 * HH];
__device__ __align__(16) __half g_w1_h[NFF * HH];
__device__ __align__(16) __half g_w1_l[NFF * HH];

// ---------------- helpers ---------------------------------------------------
__device__ __forceinline__ uint32_t smem_u32(const void* p) {
    uint32_t a;
    asm("{ .reg .u64 t; cvta.to.shared.u64 t, %1; cvt.u32.u64 %0, t; }"
        : "=r"(a) : "l"(p));
    return a;
}
__device__ __forceinline__ void split1(float x, __half& h, __half& l) {
    h = __float2half_rn(x);
    l = __float2half_rn(x - __half2float(h));
}
__device__ __forceinline__ void ldsm4(uint32_t& r0, uint32_t& r1,
                                      uint32_t& r2, uint32_t& r3, uint32_t addr) {
    asm volatile("ldmatrix.sync.aligned.m8n8.x4.shared.b16 {%0,%1,%2,%3}, [%4];"
                 : "=r"(r0), "=r"(r1), "=r"(r2), "=r"(r3) : "r"(addr));
}
__device__ __forceinline__ void hmma(float* d, const uint32_t* a,
                                     uint32_t b0, uint32_t b1) {
    asm volatile(
        "mma.sync.aligned.m16n8k16.row.col.f32.f16.f16.f32 "
        "{%0,%1,%2,%3}, {%4,%5,%6,%7}, {%8,%9}, {%0,%1,%2,%3};"
        : "+f"(d[0]), "+f"(d[1]), "+f"(d[2]), "+f"(d[3])
        : "r"(a[0]), "r"(a[1]), "r"(a[2]), "r"(a[3]), "r"(b0), "r"(b1));
}
__device__ __forceinline__ void cpasync16(uint32_t dst, const void* src) {
    asm volatile("cp.async.cg.shared.global [%0], [%1], 16;" :: "r"(dst), "l"(src));
}

// smem plane: 128 rows x 32 fp16 = 64B/row; XOR swizzle keeps LDGSTS stores and
// ldmatrix reads conflict-free without padding.
#define STAGES  3
#define PL      8192            // one plane: 128*64B
#define STG     (4 * PL)        // Ah, Al, Wh, Wl
#define SMEM_DYN (STAGES * STG) // 96 KB

__device__ __forceinline__ uint32_t sw_addr(uint32_t base, int row, int cgrp) {
    return base + row * 64 + (uint32_t)((cgrp ^ ((row >> 1) & 3)) << 4);
}

// =====================  split-fp16 HMMA GEMM, cp.async 3-stage  =============
// C[B,N] = A @ W^T + bias; A,W given as fp16 hi/lo planes.
// PASSES=3: hh + hl + lh (~fp32). PASSES=2: (hi+lo)*W_hi (~2^-12).
// STORE_C: write fp32 C. WSPLITS: write hi/lo planes of C and relu(C).
// FUSED: no store; reduce relu(tile) against w2 into partials [B,16,4].
template <int STORE_C, int WSPLITS, int PASSES, int FUSED>
__global__ __launch_bounds__(256, 2)
void hgemm(const __half* __restrict__ Ah, const __half* __restrict__ Al, int lda,
           const __half* __restrict__ Wh, const __half* __restrict__ Wl, int K,
           const float* __restrict__ bias, float* __restrict__ C, int N,
           __half* __restrict__ Oh, __half* __restrict__ Ol,
           __half* __restrict__ Rh, __half* __restrict__ Rl,
           const float* __restrict__ w2g, float* __restrict__ part)
{
    extern __shared__ char dsm[];
    const uint32_t sb = smem_u32(dsm);

    const int tid  = threadIdx.x;
    const int wid  = tid >> 5;
    const int lane = tid & 31;
    const int wm   = wid & 1;
    const int wn   = wid >> 1;
    const int grp  = lane >> 3;
    const int wi   = lane & 7;

    const __half* Abh = Ah + (size_t)blockIdx.y * 128 * lda;
    const __half* Abl = Al + (size_t)blockIdx.y * 128 * lda;
    const __half* Wbh = Wh + (size_t)blockIdx.x * 128 * K;
    const __half* Wbl = Wl + (size_t)blockIdx.x * 128 * K;

    const int r0c = tid >> 2, cg0 = tid & 3;
    const int r1c = (tid + 256) >> 2, cg1 = tid & 3;

    const int rowA0 = wm * 64 + (grp & 1) * 8 + wi;
    const int sA    = (rowA0 >> 1) & 3;
    const int cA    = grp >> 1;
    const int rowW0 = wn * 32 + (grp >> 1) * 8 + wi;
    const int sW    = (rowW0 >> 1) & 3;
    const int cW    = grp & 1;

    float acc[4][4][4];
#pragma unroll
    for (int mt = 0; mt < 4; ++mt)
#pragma unroll
        for (int nt = 0; nt < 4; ++nt)
#pragma unroll
            for (int r = 0; r < 4; ++r) acc[mt][nt][r] = 0.f;

    const int nchunk = K >> 5;   // K / 32

#define ISSUE(c) do {                                                          \
    int k0_ = (c) << 5;                                                        \
    uint32_t stg_ = sb + (uint32_t)((c) % STAGES) * STG;                       \
    uint32_t d0_ = sw_addr(stg_, r0c, cg0);                                    \
    cpasync16(d0_,          Abh + (size_t)r0c * lda + k0_ + cg0 * 8);          \
    cpasync16(d0_ + PL,     Abl + (size_t)r0c * lda + k0_ + cg0 * 8);          \
    cpasync16(d0_ + 2*PL,   Wbh + (size_t)r0c * K  + k0_ + cg0 * 8);           \
    if (PASSES == 3)                                                           \
        cpasync16(d0_ + 3*PL, Wbl + (size_t)r0c * K + k0_ + cg0 * 8);          \
    uint32_t d1_ = sw_addr(stg_, r1c, cg1);                                    \
    cpasync16(d1_,          Abh + (size_t)r1c * lda + k0_ + cg1 * 8);          \
    cpasync16(d1_ + PL,     Abl + (size_t)r1c * lda + k0_ + cg1 * 8);          \
    cpasync16(d1_ + 2*PL,   Wbh + (size_t)r1c * K  + k0_ + cg1 * 8);           \
    if (PASSES == 3)                                                           \
        cpasync16(d1_ + 3*PL, Wbl + (size_t)r1c * K + k0_ + cg1 * 8);          \
} while (0)

#pragma unroll
    for (int s = 0; s < STAGES - 1; ++s) {
        ISSUE(s);
        asm volatile("cp.async.commit_group;");
    }

    for (int c = 0; c < nchunk; ++c) {
        asm volatile("cp.async.wait_group %0;" :: "n"(STAGES - 2));
        __syncthreads();
        if (c + STAGES - 1 < nchunk) ISSUE(c + STAGES - 1);
        asm volatile("cp.async.commit_group;");

        const uint32_t stg = sb + (uint32_t)(c % STAGES) * STG;
#pragma unroll
        for (int ks = 0; ks < 2; ++ks) {
            uint32_t bh[4][2], bl[4][2];
#pragma unroll
            for (int nh = 0; nh < 2; ++nh) {
                uint32_t wd = stg + 2 * PL + (uint32_t)(rowW0 + nh * 16) * 64
                            + (uint32_t)(((ks * 2 + cW) ^ sW) << 4);
                uint32_t r0, r1, r2, r3;
                ldsm4(r0, r1, r2, r3, wd);
                bh[nh * 2 + 0][0] = r0; bh[nh * 2 + 0][1] = r1;
                bh[nh * 2 + 1][0] = r2; bh[nh * 2 + 1][1] = r3;
                if (PASSES == 3) {
                    ldsm4(r0, r1, r2, r3, wd + PL);
                    bl[nh * 2 + 0][0] = r0; bl[nh * 2 + 0][1] = r1;
                    bl[nh * 2 + 1][0] = r2; bl[nh * 2 + 1][1] = r3;
                }
            }
            uint32_t a[4][4];
#pragma unroll
            for (int mt = 0; mt < 4; ++mt) {
                uint32_t ad = stg + (uint32_t)(rowA0 + mt * 16) * 64
                            + (uint32_t)(((ks * 2 + cA) ^ sA) << 4);
                ldsm4(a[mt][0], a[mt][1], a[mt][2], a[mt][3], ad);
#pragma unroll
                for (int nt = 0; nt < 4; ++nt) {
                    hmma(acc[mt][nt], a[mt], bh[nt][0], bh[nt][1]);
                    if (PASSES == 3)
                        hmma(acc[mt][nt], a[mt], bl[nt][0], bl[nt][1]);
                }
            }
#pragma unroll
            for (int mt = 0; mt < 4; ++mt) {
                uint32_t ad = stg + PL + (uint32_t)(rowA0 + mt * 16) * 64
                            + (uint32_t)(((ks * 2 + cA) ^ sA) << 4);
                ldsm4(a[mt][0], a[mt][1], a[mt][2], a[mt][3], ad);
#pragma unroll
                for (int nt = 0; nt < 4; ++nt)
                    hmma(acc[mt][nt], a[mt], bh[nt][0], bh[nt][1]);
            }
        }
    }
#undef ISSUE

    if (FUSED) {
        // ---- fused mlp2: relu(tile) . w2 -> partials [B, 16, 4] ------------
        __syncthreads();                       // pipeline smem now reusable
        float* w2s = (float*)dsm;              // [4][128]
        float* red = (float*)(dsm + 2048);     // [4 warps-n][128 rows][4 outs]
        if (tid < 128) {
#pragma unroll
            for (int o = 0; o < 4; ++o)
                w2s[o * 128 + tid] = w2g[(size_t)o * NFF + blockIdx.x * 128 + tid];
        }
        __syncthreads();

        float po[8][4];
#pragma unroll
        for (int i = 0; i < 8; ++i)
#pragma unroll
            for (int o = 0; o < 4; ++o) po[i][o] = 0.f;

#pragma unroll
        for (int mt = 0; mt < 4; ++mt) {
#pragma unroll
            for (int nt = 0; nt < 4; ++nt) {
                const int clb = wn * 32 + (lane & 3) * 2 + nt * 8;
                const float b0 = bias[blockIdx.x * 128 + clb];
                const float b1v = bias[blockIdx.x * 128 + clb + 1];
                float t00 = fmaxf(acc[mt][nt][0] + b0, 0.f);
                float t01 = fmaxf(acc[mt][nt][1] + b1v, 0.f);
                float t10 = fmaxf(acc[mt][nt][2] + b0, 0.f);
                float t11 = fmaxf(acc[mt][nt][3] + b1v, 0.f);
#pragma unroll
                for (int o = 0; o < 4; ++o) {
                    float w0 = w2s[o * 128 + clb], w1w = w2s[o * 128 + clb + 1];
                    po[mt * 2 + 0][o] += t00 * w0 + t01 * w1w;
                    po[mt * 2 + 1][o] += t10 * w0 + t11 * w1w;
                }
            }
        }
#pragma unroll
        for (int off = 1; off <= 2; off <<= 1)
#pragma unroll
            for (int i = 0; i < 8; ++i)
#pragma unroll
                for (int o = 0; o < 4; ++o)
                    po[i][o] += __shfl_xor_sync(0xffffffffu, po[i][o], off);

        if ((lane & 3) == 0) {
            const int rq = lane >> 2;
#pragma unroll
            for (int i = 0; i < 8; ++i) {
                int row = wm * 64 + rq + (i >> 1) * 16 + (i & 1) * 8;
#pragma unroll
                for (int o = 0; o < 4; ++o)
                    red[(wn * 128 + row) * 4 + o] = po[i][o];
            }
        }
        __syncthreads();
        if (tid < 128) {
            float4 s = make_float4(0.f, 0.f, 0.f, 0.f);
#pragma unroll
            for (int w = 0; w < 4; ++w) {
                float4 v = *(float4*)&red[(w * 128 + tid) * 4];
                s.x += v.x; s.y += v.y; s.z += v.z; s.w += v.w;
            }
            *(float4*)(part + ((size_t)(blockIdx.y * 128 + tid) * 16
                               + blockIdx.x) * 4) = s;
        }
        return;
    }

    // ---- standard epilogue -------------------------------------------------
    const int row0 = blockIdx.y * 128 + wm * 64 + (lane >> 2);
    const int col0 = blockIdx.x * 128 + wn * 32 + (lane & 3) * 2;
#pragma unroll
    for (int mt = 0; mt < 4; ++mt) {
#pragma unroll
        for (int nt = 0; nt < 4; ++nt) {
            const int cI = col0 + nt * 8;
            const float b0 = bias[cI], b1 = bias[cI + 1];
            float2 v0, v1;
            v0.x = acc[mt][nt][0] + b0; v0.y = acc[mt][nt][1] + b1;
            v1.x = acc[mt][nt][2] + b0; v1.y = acc[mt][nt][3] + b1;
            const int r = row0 + mt * 16;
            if (STORE_C) {
                *(float2*)(C + (size_t)r * N + cI)       = v0;
                *(float2*)(C + (size_t)(r + 8) * N + cI) = v1;
            }
            if (WSPLITS) {
                __half h0, l0, h1, l1;
                split1(v0.x, h0, l0); split1(v0.y, h1, l1);
                *(__half2*)(Oh + (size_t)r * N + cI) = __halves2half2(h0, h1);
                *(__half2*)(Ol + (size_t)r * N + cI) = __halves2half2(l0, l1);
                split1(v1.x, h0, l0); split1(v1.y, h1, l1);
                *(__half2*)(Oh + (size_t)(r + 8) * N + cI) = __halves2half2(h0, h1);
                *(__half2*)(Ol + (size_t)(r + 8) * N + cI) = __halves2half2(l0, l1);
                float r0x = fmaxf(v0.x, 0.f), r0y = fmaxf(v0.y, 0.f);
                float r1x = fmaxf(v1.x, 0.f), r1y = fmaxf(v1.y, 0.f);
                split1(r0x, h0, l0); split1(r0y, h1, l1);
                *(__half2*)(Rh + (size_t)r * N + cI) = __halves2half2(h0, h1);
                *(__half2*)(Rl + (size_t)r * N + cI) = __halves2half2(l0, l1);
                split1(r1x, h0, l0); split1(r1y, h1, l1);
                *(__half2*)(Rh + (size_t)(r + 8) * N + cI) = __halves2half2(h0, h1);
                *(__half2*)(Rl + (size_t)(r + 8) * N + cI) = __halves2half2(l0, l1);
            }
        }
    }
}

// ---------------- prep: all weight/state splits + xy zero, ONE launch -------
__global__ void prep_kernel(const float* __restrict__ whh, const float* __restrict__ wfc,
                            const float* __restrict__ w1f, const float* __restrict__ ptf,
                            __half* __restrict__ whh_h, __half* __restrict__ whh_l,
                            __half* __restrict__ wfc_h, __half* __restrict__ wfc_l,
                            __half* __restrict__ w1_h,  __half* __restrict__ w1_l,
                            __half* __restrict__ hp_h,  __half* __restrict__ hp_l,
                            float* __restrict__ xy)
{
    const int n0 = 3 * HH * HH;
    const int n1 = n0 + HH * 2 * HH;
    const int n2 = n1 + NFF * HH;
    const int n3 = n2 + NB * HH;
    const int n4 = n3 + NB * NOUT;
    int i = (blockIdx.x * blockDim.x + threadIdx.x) * 4;
    if (i >= n4) return;
    if (i >= n3) {
        *(float4*)(xy + (i - n3)) = make_float4(0.f, 0.f, 0.f, 0.f);
        return;
    }
    const float* src; __half *hi, *lo; int off;
    if (i < n0)      { src = whh; hi = whh_h; lo = whh_l; off = i; }
    else if (i < n1) { src = wfc; hi = wfc_h; lo = wfc_l; off = i - n0; }
    else if (i < n2) { src = w1f; hi = w1_h;  lo = w1_l;  off = i - n1; }
    else             { src = ptf; hi = hp_h;  lo = hp_l;  off = i - n2; }
    float4 v = *(const float4*)(src + off);
    __half h0, l0, h1, l1, h2, l2, h3, l3;
    split1(v.x, h0, l0); split1(v.y, h1, l1);
    split1(v.z, h2, l2); split1(v.w, h3, l3);
    *(__half2*)(hi + off)     = __halves2half2(h0, h1);
    *(__half2*)(hi + off + 2) = __halves2half2(h2, h3);
    *(__half2*)(lo + off)     = __halves2half2(l0, l1);
    *(__half2*)(lo + off + 2) = __halves2half2(l2, l3);
}

// ---------------- GRU gate fusion (r,z,n order); planes in, planes out ------
__global__ void gru_gates_kernel(const float* __restrict__ gh,
                                 const float* __restrict__ x, int ldx,
                                 const __half* __restrict__ php,  // hprev hi
                                 const __half* __restrict__ plp,  // hprev lo
                                 int ldh,
                                 const float* __restrict__ w_ih,  // [3H,4]
                                 const float* __restrict__ b_ih,  // [3H]
                                 __half* __restrict__ ph,         // out hi plane
                                 __half* __restrict__ pl,         // out lo plane
                                 int ldp)
{
    int j = blockIdx.x * blockDim.x + threadIdx.x;   // 0..H-1
    int b = blockIdx.y;
    float4 xv = *(const float4*)(x + (size_t)b * ldx);

    float ig[3];
#pragma unroll
    for (int g = 0; g < 3; ++g) {
        int rI = g * HH + j;
        float4 w = *(const float4*)(w_ih + (size_t)rI * 4);
        ig[g] = b_ih[rI] + xv.x * w.x + xv.y * w.y + xv.z * w.z + xv.w * w.w;
    }
    const float* ghb = gh + (size_t)b * (3 * HH);
    float gr = ghb[j], gz = ghb[HH + j], gn = ghb[2 * HH + j];
    float r = 1.f / (1.f + expf(-(ig[0] + gr)));
    float z = 1.f / (1.f + expf(-(ig[1] + gz)));
    float n = tanhf(ig[2] + r * gn);
    float hp = __half2float(php[(size_t)b * ldh + j])
             + __half2float(plp[(size_t)b * ldh + j]);
    float h = (1.f - z) * n + z * hp;

    __half hh_, hl_;
    split1(h, hh_, hl_);
    ph[(size_t)b * ldp + j] = hh_;
    pl[(size_t)b * ldp + j] = hl_;
}

// ---------------- finalize: sum partials, update xy, write out --------------
__global__ void finalize_kernel(const float* __restrict__ part,
                                const float* __restrict__ b2,
                                float* __restrict__ xy,
                                float* __restrict__ out, int step)
{
    int b = blockIdx.x * blockDim.x + threadIdx.x;
    if (b >= NB) return;
    const float4* p = (const float4*)(part + (size_t)b * 64);
    float4 s = p[0];
#pragma unroll
    for (int j = 1; j < 16; ++j) {
        float4 v = p[j];
        s.x += v.x; s.y += v.y; s.z += v.z; s.w += v.w;
    }
    float4 cur = *(float4*)(xy + (size_t)b * 4);
    cur.x += s.x + b2[0];
    cur.y += s.y + b2[1];
    cur.z += s.z + b2[2];
    cur.w += s.w + b2[3];
    *(float4*)(xy + (size_t)b * 4) = cur;
    *(float4*)(out + (size_t)b * NHOR * NOUT + step * NOUT) = cur;
}

// ---------------- launch -----------------------------------------------------
extern "C" void kernel_launch(void* const* d_in, const int* in_sizes, int n_in,
                              void* d_out, int out_size)
{
    const float* pv   = (const float*)d_in[0];
    const float* ptf  = (const float*)d_in[1];
    const float* w_ih = (const float*)d_in[2];
    const float* w_hh = (const float*)d_in[3];
    const float* b_ih = (const float*)d_in[4];
    const float* b_hh = (const float*)d_in[5];
    const float* w_fc = (const float*)d_in[6];
    const float* b_fc = (const float*)d_in[7];
    const float* w1   = (const float*)d_in[8];
    const float* b1   = (const float*)d_in[9];
    const float* w2   = (const float*)d_in[10];
    const float* b2   = (const float*)d_in[11];
    float* out = (float*)d_out;

    float *gh, *xy, *part;
    __half *hp_h, *hp_l, *hc_h, *hc_l, *hr_h, *hr_l;
    __half *whh_h, *whh_l, *wfc_h, *wfc_l, *w1_h, *w1_l;
    cudaGetSymbolAddress((void**)&gh, g_gh);
    cudaGetSymbolAddress((void**)&xy, g_xy);
    cudaGetSymbolAddress((void**)&part, g_part);
    cudaGetSymbolAddress((void**)&hp_h, g_hp_h);
    cudaGetSymbolAddress((void**)&hp_l, g_hp_l);
    cudaGetSymbolAddress((void**)&hc_h, g_hc_h);
    cudaGetSymbolAddress((void**)&hc_l, g_hc_l);
    cudaGetSymbolAddress((void**)&hr_h, g_hr_h);
    cudaGetSymbolAddress((void**)&hr_l, g_hr_l);
    cudaGetSymbolAddress((void**)&whh_h, g_whh_h);
    cudaGetSymbolAddress((void**)&whh_l, g_whh_l);
    cudaGetSymbolAddress((void**)&wfc_h, g_wfc_h);
    cudaGetSymbolAddress((void**)&wfc_l, g_wfc_l);
    cudaGetSymbolAddress((void**)&w1_h, g_w1_h);
    cudaGetSymbolAddress((void**)&w1_l, g_w1_l);

    cudaFuncSetAttribute(hgemm<1, 0, 3, 0>, cudaFuncAttributeMaxDynamicSharedMemorySize, SMEM_DYN);
    cudaFuncSetAttribute(hgemm<0, 1, 3, 0>, cudaFuncAttributeMaxDynamicSharedMemorySize, SMEM_DYN);
    cudaFuncSetAttribute(hgemm<0, 0, 2, 1>, cudaFuncAttributeMaxDynamicSharedMemorySize, SMEM_DYN);

    // ---- side stream + per-step fork/join events (host-side handles only;
    // created once, reused deterministically on every call) ----
    static cudaStream_t sS = nullptr;
    static cudaEvent_t evFC[NHOR], evFin[NHOR];
    if (!sS) {
        cudaStreamCreateWithFlags(&sS, cudaStreamNonBlocking);
        for (int i = 0; i < NHOR; ++i) {
            cudaEventCreateWithFlags(&evFC[i], cudaEventDisableTiming);
            cudaEventCreateWithFlags(&evFin[i], cudaEventDisableTiming);
        }
    }

    // ---- prep (single launch): split weights + ptf, zero xy ----
    {
        const int n4 = 3 * HH * HH + HH * 2 * HH + NFF * HH + NB * HH + NB * NOUT;
        prep_kernel<<<(n4 / 4 + 255) / 256, 256>>>(
            w_hh, w_fc, w1, ptf,
            whh_h, whh_l, wfc_h, wfc_l, w1_h, w1_l, hp_h, hp_l, xy);
    }

    for (int i = 0; i < NHOR; ++i) {
        // cell 1 GEMM: gh = hprev @ w_hh^T + b_hh
        // (depends only on hp planes from fc(i-1); overlaps MLP branch of i-1)
        hgemm<1, 0, 3, 0><<<dim3(3 * HH / 128, NB / 128), 256, SMEM_DYN>>>(
            hp_h, hp_l, HH, whh_h, whh_l, HH, b_hh, gh, 3 * HH,
            nullptr, nullptr, nullptr, nullptr, nullptr, nullptr);

        // gates1 needs xy -> join with finalize(i-1) on side stream
        if (i > 0) cudaStreamWaitEvent(0, evFin[i - 1], 0);
        gru_gates_kernel<<<dim3(HH / 256, NB), 256>>>(
            gh, xy, NOUT, hp_h, hp_l, HH, w_ih, b_ih,
            hc_h, hc_l, 2 * HH);

        // cell 2: gh = h1 @ w_hh^T + b_hh ; h2 = gates(pv_i, gh, h1)
        hgemm<1, 0, 3, 0><<<dim3(3 * HH / 128, NB / 128), 256, SMEM_DYN>>>(
            hc_h, hc_l, 2 * HH, whh_h, whh_l, HH, b_hh, gh, 3 * HH,
            nullptr, nullptr, nullptr, nullptr, nullptr, nullptr);
        gru_gates_kernel<<<dim3(HH / 256, NB), 256>>>(
            gh, pv + i * NOUT, NHOR * NOUT, hc_h, hc_l, 2 * HH, w_ih, b_ih,
            hc_h + HH, hc_l + HH, 2 * HH);

        // hx = hcat @ w_fc^T + b_fc ; emit hp planes + relu planes
        hgemm<0, 1, 3, 0><<<dim3(HH / 128, NB / 128), 256, SMEM_DYN>>>(
            hc_h, hc_l, 2 * HH, wfc_h, wfc_l, 2 * HH, b_fc, nullptr, HH,
            hp_h, hp_l, hr_h, hr_l, nullptr, nullptr);
        cudaEventRecord(evFC[i], 0);

        // ---- MLP branch on side stream (overlaps next step's cell-1 GEMM) --
        cudaStreamWaitEvent(sS, evFC[i], 0);
        hgemm<0, 0, 2, 1><<<dim3(NFF / 128, NB / 128), 256, SMEM_DYN, sS>>>(
            hr_h, hr_l, HH, w1_h, w1_l, HH, b1, nullptr, NFF,
            nullptr, nullptr, nullptr, nullptr, w2, part);
        finalize_kernel<<<(NB + 255) / 256, 256, 0, sS>>>(part, b2, xy, out, i);
        cudaEventRecord(evFin[i], sS);
    }
    // join the last MLP branch back into the capture stream
    cudaStreamWaitEvent(0, evFin[NHOR - 1], 0);
}

// round 13
// speedup vs baseline: 1.2476x; 1.1478x over previous
#include <cuda_runtime.h>
#include <cuda_fp16.h>
#include <math.h>
#include <stdint.h>

#define NB   16384
#define HH   512
#define NOUT 4
#define NFF  2048
#define NHOR 5

// ---------------- fp32 scratch ----------------------------------------------
__device__ float g_gh[(size_t)NB * 3 * HH];       // gate pre-activations [B,3H]
__device__ float g_xy[(size_t)NB * NOUT];         // running xy
__device__ float g_part[(size_t)NB * 16 * NOUT];  // mlp partials [B,16,4]

// ---------------- fp16 hi/lo planes (GEMM operands) -------------------------
__device__ __align__(16) __half g_hp_h[(size_t)NB * HH];      // hprev (hx)
__device__ __align__(16) __half g_hp_l[(size_t)NB * HH];
__device__ __align__(16) __half g_hc_h[(size_t)NB * 2 * HH];  // hcat [h1|h2]
__device__ __align__(16) __half g_hc_l[(size_t)NB * 2 * HH];
__device__ __align__(16) __half g_hr_h[(size_t)NB * HH];      // relu(hx)
__device__ __align__(16) __half g_hr_l[(size_t)NB * HH];
__device__ __align__(16) __half g_whh_h[3 * HH * HH];
__device__ __align__(16) __half g_whh_l[3 * HH * HH];
__device__ __align__(16) __half g_wfc_h[HH * 2 * HH];
__device__ __align__(16) __half g_wfc_l[HH * 2 * HH];
__device__ __align__(16) __half g_w1_h[NFF * HH];
__device__ __align__(16) __half g_w1_l[NFF * HH];

// ---------------- helpers ---------------------------------------------------
__device__ __forceinline__ uint32_t smem_u32(const void* p) {
    uint32_t a;
    asm("{ .reg .u64 t; cvta.to.shared.u64 t, %1; cvt.u32.u64 %0, t; }"
        : "=r"(a) : "l"(p));
    return a;
}
__device__ __forceinline__ void split1(float x, __half& h, __half& l) {
    h = __float2half_rn(x);
    l = __float2half_rn(x - __half2float(h));
}
__device__ __forceinline__ void ldsm4(uint32_t& r0, uint32_t& r1,
                                      uint32_t& r2, uint32_t& r3, uint32_t addr) {
    asm volatile("ldmatrix.sync.aligned.m8n8.x4.shared.b16 {%0,%1,%2,%3}, [%4];"
                 : "=r"(r0), "=r"(r1), "=r"(r2), "=r"(r3) : "r"(addr));
}
__device__ __forceinline__ void hmma(float* d, const uint32_t* a,
                                     uint32_t b0, uint32_t b1) {
    asm volatile(
        "mma.sync.aligned.m16n8k16.row.col.f32.f16.f16.f32 "
        "{%0,%1,%2,%3}, {%4,%5,%6,%7}, {%8,%9}, {%0,%1,%2,%3};"
        : "+f"(d[0]), "+f"(d[1]), "+f"(d[2]), "+f"(d[3])
        : "r"(a[0]), "r"(a[1]), "r"(a[2]), "r"(a[3]), "r"(b0), "r"(b1));
}
__device__ __forceinline__ void cpasync16(uint32_t dst, const void* src) {
    asm volatile("cp.async.cg.shared.global [%0], [%1], 16;" :: "r"(dst), "l"(src));
}

// smem plane: 128 rows x 32 fp16 = 64B/row; XOR swizzle keeps LDGSTS stores and
// ldmatrix reads conflict-free without padding.
#define STAGES  3
#define PL      8192            // one plane: 128*64B
#define STG     (4 * PL)        // Ah, Al, Wh, Wl
#define SMEM_DYN (STAGES * STG) // 96 KB

__device__ __forceinline__ uint32_t sw_addr(uint32_t base, int row, int cgrp) {
    return base + row * 64 + (uint32_t)((cgrp ^ ((row >> 1) & 3)) << 4);
}

// =====================  split-fp16 HMMA GEMM, cp.async 3-stage  =============
// C[B,N] = A @ W^T + bias; A,W given as fp16 hi/lo planes.
// PASSES=3: hh + hl + lh (~fp32). PASSES=2: (A_hi+A_lo)*W_hi (~2^-12 on W).
// STORE_C: write fp32 C. WSPLITS: write hi/lo planes of C and relu(C).
// FUSED: no store; reduce relu(tile) against w2 into partials [B,16,4].
template <int STORE_C, int WSPLITS, int PASSES, int FUSED>
__global__ __launch_bounds__(256, 2)
void hgemm(const __half* __restrict__ Ah, const __half* __restrict__ Al, int lda,
           const __half* __restrict__ Wh, const __half* __restrict__ Wl, int K,
           const float* __restrict__ bias, float* __restrict__ C, int N,
           __half* __restrict__ Oh, __half* __restrict__ Ol,
           __half* __restrict__ Rh, __half* __restrict__ Rl,
           const float* __restrict__ w2g, float* __restrict__ part)
{
    extern __shared__ char dsm[];
    const uint32_t sb = smem_u32(dsm);

    const int tid  = threadIdx.x;
    const int wid  = tid >> 5;
    const int lane = tid & 31;
    const int wm   = wid & 1;
    const int wn   = wid >> 1;
    const int grp  = lane >> 3;
    const int wi   = lane & 7;

    const __half* Abh = Ah + (size_t)blockIdx.y * 128 * lda;
    const __half* Abl = Al + (size_t)blockIdx.y * 128 * lda;
    const __half* Wbh = Wh + (size_t)blockIdx.x * 128 * K;
    const __half* Wbl = Wl + (size_t)blockIdx.x * 128 * K;

    const int r0c = tid >> 2, cg0 = tid & 3;
    const int r1c = (tid + 256) >> 2, cg1 = tid & 3;

    const int rowA0 = wm * 64 + (grp & 1) * 8 + wi;
    const int sA    = (rowA0 >> 1) & 3;
    const int cA    = grp >> 1;
    const int rowW0 = wn * 32 + (grp >> 1) * 8 + wi;
    const int sW    = (rowW0 >> 1) & 3;
    const int cW    = grp & 1;

    float acc[4][4][4];
#pragma unroll
    for (int mt = 0; mt < 4; ++mt)
#pragma unroll
        for (int nt = 0; nt < 4; ++nt)
#pragma unroll
            for (int r = 0; r < 4; ++r) acc[mt][nt][r] = 0.f;

    const int nchunk = K >> 5;   // K / 32

#define ISSUE(c) do {                                                          \
    int k0_ = (c) << 5;                                                        \
    uint32_t stg_ = sb + (uint32_t)((c) % STAGES) * STG;                       \
    uint32_t d0_ = sw_addr(stg_, r0c, cg0);                                    \
    cpasync16(d0_,          Abh + (size_t)r0c * lda + k0_ + cg0 * 8);          \
    cpasync16(d0_ + PL,     Abl + (size_t)r0c * lda + k0_ + cg0 * 8);          \
    cpasync16(d0_ + 2*PL,   Wbh + (size_t)r0c * K  + k0_ + cg0 * 8);           \
    if (PASSES == 3)                                                           \
        cpasync16(d0_ + 3*PL, Wbl + (size_t)r0c * K + k0_ + cg0 * 8);          \
    uint32_t d1_ = sw_addr(stg_, r1c, cg1);                                    \
    cpasync16(d1_,          Abh + (size_t)r1c * lda + k0_ + cg1 * 8);          \
    cpasync16(d1_ + PL,     Abl + (size_t)r1c * lda + k0_ + cg1 * 8);          \
    cpasync16(d1_ + 2*PL,   Wbh + (size_t)r1c * K  + k0_ + cg1 * 8);           \
    if (PASSES == 3)                                                           \
        cpasync16(d1_ + 3*PL, Wbl + (size_t)r1c * K + k0_ + cg1 * 8);          \
} while (0)

#pragma unroll
    for (int s = 0; s < STAGES - 1; ++s) {
        ISSUE(s);
        asm volatile("cp.async.commit_group;");
    }

    for (int c = 0; c < nchunk; ++c) {
        asm volatile("cp.async.wait_group %0;" :: "n"(STAGES - 2));
        __syncthreads();
        if (c + STAGES - 1 < nchunk) ISSUE(c + STAGES - 1);
        asm volatile("cp.async.commit_group;");

        const uint32_t stg = sb + (uint32_t)(c % STAGES) * STG;
#pragma unroll
        for (int ks = 0; ks < 2; ++ks) {
            uint32_t bh[4][2], bl[4][2];
#pragma unroll
            for (int nh = 0; nh < 2; ++nh) {
                uint32_t wd = stg + 2 * PL + (uint32_t)(rowW0 + nh * 16) * 64
                            + (uint32_t)(((ks * 2 + cW) ^ sW) << 4);
                uint32_t r0, r1, r2, r3;
                ldsm4(r0, r1, r2, r3, wd);
                bh[nh * 2 + 0][0] = r0; bh[nh * 2 + 0][1] = r1;
                bh[nh * 2 + 1][0] = r2; bh[nh * 2 + 1][1] = r3;
                if (PASSES == 3) {
                    ldsm4(r0, r1, r2, r3, wd + PL);
                    bl[nh * 2 + 0][0] = r0; bl[nh * 2 + 0][1] = r1;
                    bl[nh * 2 + 1][0] = r2; bl[nh * 2 + 1][1] = r3;
                }
            }
            uint32_t a[4][4];
#pragma unroll
            for (int mt = 0; mt < 4; ++mt) {
                uint32_t ad = stg + (uint32_t)(rowA0 + mt * 16) * 64
                            + (uint32_t)(((ks * 2 + cA) ^ sA) << 4);
                ldsm4(a[mt][0], a[mt][1], a[mt][2], a[mt][3], ad);
#pragma unroll
                for (int nt = 0; nt < 4; ++nt) {
                    hmma(acc[mt][nt], a[mt], bh[nt][0], bh[nt][1]);
                    if (PASSES == 3)
                        hmma(acc[mt][nt], a[mt], bl[nt][0], bl[nt][1]);
                }
            }
#pragma unroll
            for (int mt = 0; mt < 4; ++mt) {
                uint32_t ad = stg + PL + (uint32_t)(rowA0 + mt * 16) * 64
                            + (uint32_t)(((ks * 2 + cA) ^ sA) << 4);
                ldsm4(a[mt][0], a[mt][1], a[mt][2], a[mt][3], ad);
#pragma unroll
                for (int nt = 0; nt < 4; ++nt)
                    hmma(acc[mt][nt], a[mt], bh[nt][0], bh[nt][1]);
            }
        }
    }
#undef ISSUE

    if (FUSED) {
        // ---- fused mlp2: relu(tile) . w2 -> partials [B, 16, 4] ------------
        __syncthreads();                       // pipeline smem now reusable
        float* w2s = (float*)dsm;              // [4][128]
        float* red = (float*)(dsm + 2048);     // [4 warps-n][128 rows][4 outs]
        if (tid < 128) {
#pragma unroll
            for (int o = 0; o < 4; ++o)
                w2s[o * 128 + tid] = w2g[(size_t)o * NFF + blockIdx.x * 128 + tid];
        }
        __syncthreads();

        float po[8][4];
#pragma unroll
        for (int i = 0; i < 8; ++i)
#pragma unroll
            for (int o = 0; o < 4; ++o) po[i][o] = 0.f;

#pragma unroll
        for (int mt = 0; mt < 4; ++mt) {
#pragma unroll
            for (int nt = 0; nt < 4; ++nt) {
                const int clb = wn * 32 + (lane & 3) * 2 + nt * 8;
                const float b0 = bias[blockIdx.x * 128 + clb];
                const float b1v = bias[blockIdx.x * 128 + clb + 1];
                float t00 = fmaxf(acc[mt][nt][0] + b0, 0.f);
                float t01 = fmaxf(acc[mt][nt][1] + b1v, 0.f);
                float t10 = fmaxf(acc[mt][nt][2] + b0, 0.f);
                float t11 = fmaxf(acc[mt][nt][3] + b1v, 0.f);
#pragma unroll
                for (int o = 0; o < 4; ++o) {
                    float w0 = w2s[o * 128 + clb], w1w = w2s[o * 128 + clb + 1];
                    po[mt * 2 + 0][o] += t00 * w0 + t01 * w1w;
                    po[mt * 2 + 1][o] += t10 * w0 + t11 * w1w;
                }
            }
        }
#pragma unroll
        for (int off = 1; off <= 2; off <<= 1)
#pragma unroll
            for (int i = 0; i < 8; ++i)
#pragma unroll
                for (int o = 0; o < 4; ++o)
                    po[i][o] += __shfl_xor_sync(0xffffffffu, po[i][o], off);

        if ((lane & 3) == 0) {
            const int rq = lane >> 2;
#pragma unroll
            for (int i = 0; i < 8; ++i) {
                int row = wm * 64 + rq + (i >> 1) * 16 + (i & 1) * 8;
#pragma unroll
                for (int o = 0; o < 4; ++o)
                    red[(wn * 128 + row) * 4 + o] = po[i][o];
            }
        }
        __syncthreads();
        if (tid < 128) {
            float4 s = make_float4(0.f, 0.f, 0.f, 0.f);
#pragma unroll
            for (int w = 0; w < 4; ++w) {
                float4 v = *(float4*)&red[(w * 128 + tid) * 4];
                s.x += v.x; s.y += v.y; s.z += v.z; s.w += v.w;
            }
            *(float4*)(part + ((size_t)(blockIdx.y * 128 + tid) * 16
                               + blockIdx.x) * 4) = s;
        }
        return;
    }

    // ---- standard epilogue -------------------------------------------------
    const int row0 = blockIdx.y * 128 + wm * 64 + (lane >> 2);
    const int col0 = blockIdx.x * 128 + wn * 32 + (lane & 3) * 2;
#pragma unroll
    for (int mt = 0; mt < 4; ++mt) {
#pragma unroll
        for (int nt = 0; nt < 4; ++nt) {
            const int cI = col0 + nt * 8;
            const float b0 = bias[cI], b1 = bias[cI + 1];
            float2 v0, v1;
            v0.x = acc[mt][nt][0] + b0; v0.y = acc[mt][nt][1] + b1;
            v1.x = acc[mt][nt][2] + b0; v1.y = acc[mt][nt][3] + b1;
            const int r = row0 + mt * 16;
            if (STORE_C) {
                *(float2*)(C + (size_t)r * N + cI)       = v0;
                *(float2*)(C + (size_t)(r + 8) * N + cI) = v1;
            }
            if (WSPLITS) {
                __half h0, l0, h1, l1;
                split1(v0.x, h0, l0); split1(v0.y, h1, l1);
                *(__half2*)(Oh + (size_t)r * N + cI) = __halves2half2(h0, h1);
                *(__half2*)(Ol + (size_t)r * N + cI) = __halves2half2(l0, l1);
                split1(v1.x, h0, l0); split1(v1.y, h1, l1);
                *(__half2*)(Oh + (size_t)(r + 8) * N + cI) = __halves2half2(h0, h1);
                *(__half2*)(Ol + (size_t)(r + 8) * N + cI) = __halves2half2(l0, l1);
                float r0x = fmaxf(v0.x, 0.f), r0y = fmaxf(v0.y, 0.f);
                float r1x = fmaxf(v1.x, 0.f), r1y = fmaxf(v1.y, 0.f);
                split1(r0x, h0, l0); split1(r0y, h1, l1);
                *(__half2*)(Rh + (size_t)r * N + cI) = __halves2half2(h0, h1);
                *(__half2*)(Rl + (size_t)r * N + cI) = __halves2half2(l0, l1);
                split1(r1x, h0, l0); split1(r1y, h1, l1);
                *(__half2*)(Rh + (size_t)(r + 8) * N + cI) = __halves2half2(h0, h1);
                *(__half2*)(Rl + (size_t)(r + 8) * N + cI) = __halves2half2(l0, l1);
            }
        }
    }
}

// ---------------- prep: all weight/state splits + xy zero, ONE launch -------
__global__ void prep_kernel(const float* __restrict__ whh, const float* __restrict__ wfc,
                            const float* __restrict__ w1f, const float* __restrict__ ptf,
                            __half* __restrict__ whh_h, __half* __restrict__ whh_l,
                            __half* __restrict__ wfc_h, __half* __restrict__ wfc_l,
                            __half* __restrict__ w1_h,  __half* __restrict__ w1_l,
                            __half* __restrict__ hp_h,  __half* __restrict__ hp_l,
                            float* __restrict__ xy)
{
    const int n0 = 3 * HH * HH;
    const int n1 = n0 + HH * 2 * HH;
    const int n2 = n1 + NFF * HH;
    const int n3 = n2 + NB * HH;
    const int n4 = n3 + NB * NOUT;
    int i = (blockIdx.x * blockDim.x + threadIdx.x) * 4;
    if (i >= n4) return;
    if (i >= n3) {
        *(float4*)(xy + (i - n3)) = make_float4(0.f, 0.f, 0.f, 0.f);
        return;
    }
    const float* src; __half *hi, *lo; int off;
    if (i < n0)      { src = whh; hi = whh_h; lo = whh_l; off = i; }
    else if (i < n1) { src = wfc; hi = wfc_h; lo = wfc_l; off = i - n0; }
    else if (i < n2) { src = w1f; hi = w1_h;  lo = w1_l;  off = i - n1; }
    else             { src = ptf; hi = hp_h;  lo = hp_l;  off = i - n2; }
    float4 v = *(const float4*)(src + off);
    __half h0, l0, h1, l1, h2, l2, h3, l3;
    split1(v.x, h0, l0); split1(v.y, h1, l1);
    split1(v.z, h2, l2); split1(v.w, h3, l3);
    *(__half2*)(hi + off)     = __halves2half2(h0, h1);
    *(__half2*)(hi + off + 2) = __halves2half2(h2, h3);
    *(__half2*)(lo + off)     = __halves2half2(l0, l1);
    *(__half2*)(lo + off + 2) = __halves2half2(l2, l3);
}

// ---------------- GRU gate fusion (r,z,n order); planes in, planes out ------
__global__ void gru_gates_kernel(const float* __restrict__ gh,
                                 const float* __restrict__ x, int ldx,
                                 const __half* __restrict__ php,  // hprev hi
                                 const __half* __restrict__ plp,  // hprev lo
                                 int ldh,
                                 const float* __restrict__ w_ih,  // [3H,4]
                                 const float* __restrict__ b_ih,  // [3H]
                                 __half* __restrict__ ph,         // out hi plane
                                 __half* __restrict__ pl,         // out lo plane
                                 int ldp)
{
    int j = blockIdx.x * blockDim.x + threadIdx.x;   // 0..H-1
    int b = blockIdx.y;
    float4 xv = *(const float4*)(x + (size_t)b * ldx);

    float ig[3];
#pragma unroll
    for (int g = 0; g < 3; ++g) {
        int rI = g * HH + j;
        float4 w = *(const float4*)(w_ih + (size_t)rI * 4);
        ig[g] = b_ih[rI] + xv.x * w.x + xv.y * w.y + xv.z * w.z + xv.w * w.w;
    }
    const float* ghb = gh + (size_t)b * (3 * HH);
    float gr = ghb[j], gz = ghb[HH + j], gn = ghb[2 * HH + j];
    float r = 1.f / (1.f + expf(-(ig[0] + gr)));
    float z = 1.f / (1.f + expf(-(ig[1] + gz)));
    float n = tanhf(ig[2] + r * gn);
    float hp = __half2float(php[(size_t)b * ldh + j])
             + __half2float(plp[(size_t)b * ldh + j]);
    float h = (1.f - z) * n + z * hp;

    __half hh_, hl_;
    split1(h, hh_, hl_);
    ph[(size_t)b * ldp + j] = hh_;
    pl[(size_t)b * ldp + j] = hl_;
}

// ---------------- finalize: sum partials, update xy, write out --------------
__global__ void finalize_kernel(const float* __restrict__ part,
                                const float* __restrict__ b2,
                                float* __restrict__ xy,
                                float* __restrict__ out, int step)
{
    int b = blockIdx.x * blockDim.x + threadIdx.x;
    if (b >= NB) return;
    const float4* p = (const float4*)(part + (size_t)b * 64);
    float4 s = p[0];
#pragma unroll
    for (int j = 1; j < 16; ++j) {
        float4 v = p[j];
        s.x += v.x; s.y += v.y; s.z += v.z; s.w += v.w;
    }
    float4 cur = *(float4*)(xy + (size_t)b * 4);
    cur.x += s.x + b2[0];
    cur.y += s.y + b2[1];
    cur.z += s.z + b2[2];
    cur.w += s.w + b2[3];
    *(float4*)(xy + (size_t)b * 4) = cur;
    *(float4*)(out + (size_t)b * NHOR * NOUT + step * NOUT) = cur;
}

// ---------------- launch -----------------------------------------------------
extern "C" void kernel_launch(void* const* d_in, const int* in_sizes, int n_in,
                              void* d_out, int out_size)
{
    const float* pv   = (const float*)d_in[0];
    const float* ptf  = (const float*)d_in[1];
    const float* w_ih = (const float*)d_in[2];
    const float* w_hh = (const float*)d_in[3];
    const float* b_ih = (const float*)d_in[4];
    const float* b_hh = (const float*)d_in[5];
    const float* w_fc = (const float*)d_in[6];
    const float* b_fc = (const float*)d_in[7];
    const float* w1   = (const float*)d_in[8];
    const float* b1   = (const float*)d_in[9];
    const float* w2   = (const float*)d_in[10];
    const float* b2   = (const float*)d_in[11];
    float* out = (float*)d_out;

    float *gh, *xy, *part;
    __half *hp_h, *hp_l, *hc_h, *hc_l, *hr_h, *hr_l;
    __half *whh_h, *whh_l, *wfc_h, *wfc_l, *w1_h, *w1_l;
    cudaGetSymbolAddress((void**)&gh, g_gh);
    cudaGetSymbolAddress((void**)&xy, g_xy);
    cudaGetSymbolAddress((void**)&part, g_part);
    cudaGetSymbolAddress((void**)&hp_h, g_hp_h);
    cudaGetSymbolAddress((void**)&hp_l, g_hp_l);
    cudaGetSymbolAddress((void**)&hc_h, g_hc_h);
    cudaGetSymbolAddress((void**)&hc_l, g_hc_l);
    cudaGetSymbolAddress((void**)&hr_h, g_hr_h);
    cudaGetSymbolAddress((void**)&hr_l, g_hr_l);
    cudaGetSymbolAddress((void**)&whh_h, g_whh_h);
    cudaGetSymbolAddress((void**)&whh_l, g_whh_l);
    cudaGetSymbolAddress((void**)&wfc_h, g_wfc_h);
    cudaGetSymbolAddress((void**)&wfc_l, g_wfc_l);
    cudaGetSymbolAddress((void**)&w1_h, g_w1_h);
    cudaGetSymbolAddress((void**)&w1_l, g_w1_l);

    cudaFuncSetAttribute(hgemm<1, 0, 2, 0>, cudaFuncAttributeMaxDynamicSharedMemorySize, SMEM_DYN);
    cudaFuncSetAttribute(hgemm<0, 1, 3, 0>, cudaFuncAttributeMaxDynamicSharedMemorySize, SMEM_DYN);
    cudaFuncSetAttribute(hgemm<0, 0, 2, 1>, cudaFuncAttributeMaxDynamicSharedMemorySize, SMEM_DYN);

    // ---- side stream + per-step fork/join events (host-side handles only;
    // created once, reused deterministically on every call) ----
    static cudaStream_t sS = nullptr;
    static cudaEvent_t evFC[NHOR], evFin[NHOR];
    if (!sS) {
        cudaStreamCreateWithFlags(&sS, cudaStreamNonBlocking);
        for (int i = 0; i < NHOR; ++i) {
            cudaEventCreateWithFlags(&evFC[i], cudaEventDisableTiming);
            cudaEventCreateWithFlags(&evFin[i], cudaEventDisableTiming);
        }
    }

    // ---- prep (single launch): split weights + ptf, zero xy ----
    {
        const int n4 = 3 * HH * HH + HH * 2 * HH + NFF * HH + NB * HH + NB * NOUT;
        prep_kernel<<<(n4 / 4 + 255) / 256, 256>>>(
            w_hh, w_fc, w1, ptf,
            whh_h, whh_l, wfc_h, wfc_l, w1_h, w1_l, hp_h, hp_l, xy);
    }

    for (int i = 0; i < NHOR; ++i) {
        // cell 1 GEMM (2-pass): gh = hprev @ w_hh^T + b_hh
        // (depends only on hp planes from fc(i-1); overlaps MLP branch of i-1)
        hgemm<1, 0, 2, 0><<<dim3(3 * HH / 128, NB / 128), 256, SMEM_DYN>>>(
            hp_h, hp_l, HH, whh_h, whh_l, HH, b_hh, gh, 3 * HH,
            nullptr, nullptr, nullptr, nullptr, nullptr, nullptr);

        // gates1 needs xy -> join with finalize(i-1) on side stream
        if (i > 0) cudaStreamWaitEvent(0, evFin[i - 1], 0);
        gru_gates_kernel<<<dim3(HH / 256, NB), 256>>>(
            gh, xy, NOUT, hp_h, hp_l, HH, w_ih, b_ih,
            hc_h, hc_l, 2 * HH);

        // cell 2 GEMM (2-pass): gh = h1 @ w_hh^T + b_hh
        hgemm<1, 0, 2, 0><<<dim3(3 * HH / 128, NB / 128), 256, SMEM_DYN>>>(
            hc_h, hc_l, 2 * HH, whh_h, whh_l, HH, b_hh, gh, 3 * HH,
            nullptr, nullptr, nullptr, nullptr, nullptr, nullptr);
        gru_gates_kernel<<<dim3(HH / 256, NB), 256>>>(
            gh, pv + i * NOUT, NHOR * NOUT, hc_h, hc_l, 2 * HH, w_ih, b_ih,
            hc_h + HH, hc_l + HH, 2 * HH);

        // hx = hcat @ w_fc^T + b_fc ; emit hp planes + relu planes (3-pass)
        hgemm<0, 1, 3, 0><<<dim3(HH / 128, NB / 128), 256, SMEM_DYN>>>(
            hc_h, hc_l, 2 * HH, wfc_h, wfc_l, 2 * HH, b_fc, nullptr, HH,
            hp_h, hp_l, hr_h, hr_l, nullptr, nullptr);
        cudaEventRecord(evFC[i], 0);

        // ---- MLP branch on side stream (overlaps next step's cell-1 GEMM) --
        cudaStreamWaitEvent(sS, evFC[i], 0);
        hgemm<0, 0, 2, 1><<<dim3(NFF / 128, NB / 128), 256, SMEM_DYN, sS>>>(
            hr_h, hr_l, HH, w1_h, w1_l, HH, b1, nullptr, NFF,
            nullptr, nullptr, nullptr, nullptr, w2, part);
        finalize_kernel<<<(NB + 255) / 256, 256, 0, sS>>>(part, b2, xy, out, i);
        cudaEventRecord(evFin[i], sS);
    }
    // join the last MLP branch back into the capture stream
    cudaStreamWaitEvent(0, evFin[NHOR - 1], 0);
}

// round 14
// speedup vs baseline: 1.3147x; 1.0537x over previous
#include <cuda_runtime.h>
#include <cuda_fp16.h>
#include <math.h>
#include <stdint.h>

#define NB   16384
#define HH   512
#define NOUT 4
#define NFF  2048
#define NHOR 5

// ---------------- fp32 scratch ----------------------------------------------
__device__ float g_gh[(size_t)NB * 3 * HH];       // gate pre-activations [B,3H]
__device__ float g_xy[(size_t)NB * NOUT];         // running xy
__device__ float g_part[(size_t)NB * 16 * NOUT];  // mlp partials [B,16,4]

// ---------------- fp16 hi/lo planes (GEMM operands) -------------------------
__device__ __align__(16) __half g_hp_h[(size_t)NB * HH];      // hprev (hx)
__device__ __align__(16) __half g_hp_l[(size_t)NB * HH];
__device__ __align__(16) __half g_hc_h[(size_t)NB * 2 * HH];  // hcat [h1|h2]
__device__ __align__(16) __half g_hc_l[(size_t)NB * 2 * HH];
__device__ __align__(16) __half g_hr_h[(size_t)NB * HH];      // relu(hx)
__device__ __align__(16) __half g_hr_l[(size_t)NB * HH];
__device__ __align__(16) __half g_whh_h[3 * HH * HH];
__device__ __align__(16) __half g_wfc_h[HH * 2 * HH];
__device__ __align__(16) __half g_w1_h[NFF * HH];

// ---------------- helpers ---------------------------------------------------
__device__ __forceinline__ uint32_t smem_u32(const void* p) {
    uint32_t a;
    asm("{ .reg .u64 t; cvta.to.shared.u64 t, %1; cvt.u32.u64 %0, t; }"
        : "=r"(a) : "l"(p));
    return a;
}
__device__ __forceinline__ void split1(float x, __half& h, __half& l) {
    h = __float2half_rn(x);
    l = __float2half_rn(x - __half2float(h));
}
__device__ __forceinline__ void ldsm4(uint32_t& r0, uint32_t& r1,
                                      uint32_t& r2, uint32_t& r3, uint32_t addr) {
    asm volatile("ldmatrix.sync.aligned.m8n8.x4.shared.b16 {%0,%1,%2,%3}, [%4];"
                 : "=r"(r0), "=r"(r1), "=r"(r2), "=r"(r3) : "r"(addr));
}
__device__ __forceinline__ void hmma(float* d, const uint32_t* a,
                                     uint32_t b0, uint32_t b1) {
    asm volatile(
        "mma.sync.aligned.m16n8k16.row.col.f32.f16.f16.f32 "
        "{%0,%1,%2,%3}, {%4,%5,%6,%7}, {%8,%9}, {%0,%1,%2,%3};"
        : "+f"(d[0]), "+f"(d[1]), "+f"(d[2]), "+f"(d[3])
        : "r"(a[0]), "r"(a[1]), "r"(a[2]), "r"(a[3]), "r"(b0), "r"(b1));
}
__device__ __forceinline__ void cpasync16(uint32_t dst, const void* src) {
    asm volatile("cp.async.cg.shared.global [%0], [%1], 16;" :: "r"(dst), "l"(src));
}

// smem plane: 128 rows x 32 fp16 = 64B/row; XOR swizzle keeps LDGSTS stores and
// ldmatrix reads conflict-free without padding.
// All GEMMs are 2-pass -> 3 planes/stage (Ah, Al, Wh); 4-stage pipeline = 96KB.
#define STAGES  4
#define PL      8192            // one plane: 128*64B
#define STG     (3 * PL)        // Ah, Al, Wh
#define SMEM_DYN (STAGES * STG) // 96 KB

__device__ __forceinline__ uint32_t sw_addr(uint32_t base, int row, int cgrp) {
    return base + row * 64 + (uint32_t)((cgrp ^ ((row >> 1) & 3)) << 4);
}

// =====================  split-fp16 HMMA GEMM, cp.async 4-stage  =============
// C[B,N] = A @ W^T + bias; A as fp16 hi/lo planes, W as truncated hi plane.
// 2-pass: (A_hi + A_lo) * W_hi  (exact A, ~2^-12 on W).
// STORE_C: write fp32 C. WSPLITS: write hi/lo planes of C and relu(C).
// FUSED: no store; reduce relu(tile) against w2 into partials [B,16,4].
template <int STORE_C, int WSPLITS, int FUSED>
__global__ __launch_bounds__(256, 2)
void hgemm(const __half* __restrict__ Ah, const __half* __restrict__ Al, int lda,
           const __half* __restrict__ Wh, int K,
           const float* __restrict__ bias, float* __restrict__ C, int N,
           __half* __restrict__ Oh, __half* __restrict__ Ol,
           __half* __restrict__ Rh, __half* __restrict__ Rl,
           const float* __restrict__ w2g, float* __restrict__ part)
{
    extern __shared__ char dsm[];
    const uint32_t sb = smem_u32(dsm);

    const int tid  = threadIdx.x;
    const int wid  = tid >> 5;
    const int lane = tid & 31;
    const int wm   = wid & 1;
    const int wn   = wid >> 1;
    const int grp  = lane >> 3;
    const int wi   = lane & 7;

    const __half* Abh = Ah + (size_t)blockIdx.y * 128 * lda;
    const __half* Abl = Al + (size_t)blockIdx.y * 128 * lda;
    const __half* Wbh = Wh + (size_t)blockIdx.x * 128 * K;

    const int r0c = tid >> 2, cg0 = tid & 3;
    const int r1c = (tid + 256) >> 2, cg1 = tid & 3;

    const int rowA0 = wm * 64 + (grp & 1) * 8 + wi;
    const int sA    = (rowA0 >> 1) & 3;
    const int cA    = grp >> 1;
    const int rowW0 = wn * 32 + (grp >> 1) * 8 + wi;
    const int sW    = (rowW0 >> 1) & 3;
    const int cW    = grp & 1;

    float acc[4][4][4];
#pragma unroll
    for (int mt = 0; mt < 4; ++mt)
#pragma unroll
        for (int nt = 0; nt < 4; ++nt)
#pragma unroll
            for (int r = 0; r < 4; ++r) acc[mt][nt][r] = 0.f;

    const int nchunk = K >> 5;   // K / 32

#define ISSUE(c) do {                                                          \
    int k0_ = (c) << 5;                                                        \
    uint32_t stg_ = sb + (uint32_t)((c) % STAGES) * STG;                       \
    uint32_t d0_ = sw_addr(stg_, r0c, cg0);                                    \
    cpasync16(d0_,          Abh + (size_t)r0c * lda + k0_ + cg0 * 8);          \
    cpasync16(d0_ + PL,     Abl + (size_t)r0c * lda + k0_ + cg0 * 8);          \
    cpasync16(d0_ + 2*PL,   Wbh + (size_t)r0c * K  + k0_ + cg0 * 8);           \
    uint32_t d1_ = sw_addr(stg_, r1c, cg1);                                    \
    cpasync16(d1_,          Abh + (size_t)r1c * lda + k0_ + cg1 * 8);          \
    cpasync16(d1_ + PL,     Abl + (size_t)r1c * lda + k0_ + cg1 * 8);          \
    cpasync16(d1_ + 2*PL,   Wbh + (size_t)r1c * K  + k0_ + cg1 * 8);           \
} while (0)

#pragma unroll
    for (int s = 0; s < STAGES - 1; ++s) {
        ISSUE(s);
        asm volatile("cp.async.commit_group;");
    }

    for (int c = 0; c < nchunk; ++c) {
        asm volatile("cp.async.wait_group %0;" :: "n"(STAGES - 2));
        __syncthreads();
        if (c + STAGES - 1 < nchunk) ISSUE(c + STAGES - 1);
        asm volatile("cp.async.commit_group;");

        const uint32_t stg = sb + (uint32_t)(c % STAGES) * STG;
#pragma unroll
        for (int ks = 0; ks < 2; ++ks) {
            uint32_t bh[4][2];
#pragma unroll
            for (int nh = 0; nh < 2; ++nh) {
                uint32_t wd = stg + 2 * PL + (uint32_t)(rowW0 + nh * 16) * 64
                            + (uint32_t)(((ks * 2 + cW) ^ sW) << 4);
                uint32_t r0, r1, r2, r3;
                ldsm4(r0, r1, r2, r3, wd);
                bh[nh * 2 + 0][0] = r0; bh[nh * 2 + 0][1] = r1;
                bh[nh * 2 + 1][0] = r2; bh[nh * 2 + 1][1] = r3;
            }
            uint32_t a[4][4];
#pragma unroll
            for (int mt = 0; mt < 4; ++mt) {
                uint32_t ad = stg + (uint32_t)(rowA0 + mt * 16) * 64
                            + (uint32_t)(((ks * 2 + cA) ^ sA) << 4);
                ldsm4(a[mt][0], a[mt][1], a[mt][2], a[mt][3], ad);
#pragma unroll
                for (int nt = 0; nt < 4; ++nt)
                    hmma(acc[mt][nt], a[mt], bh[nt][0], bh[nt][1]);
            }
#pragma unroll
            for (int mt = 0; mt < 4; ++mt) {
                uint32_t ad = stg + PL + (uint32_t)(rowA0 + mt * 16) * 64
                            + (uint32_t)(((ks * 2 + cA) ^ sA) << 4);
                ldsm4(a[mt][0], a[mt][1], a[mt][2], a[mt][3], ad);
#pragma unroll
                for (int nt = 0; nt < 4; ++nt)
                    hmma(acc[mt][nt], a[mt], bh[nt][0], bh[nt][1]);
            }
        }
    }
#undef ISSUE

    if (FUSED) {
        // ---- fused mlp2: relu(tile) . w2 -> partials [B, 16, 4] ------------
        __syncthreads();                       // pipeline smem now reusable
        float* w2s = (float*)dsm;              // [4][128]
        float* red = (float*)(dsm + 2048);     // [4 warps-n][128 rows][4 outs]
        if (tid < 128) {
#pragma unroll
            for (int o = 0; o < 4; ++o)
                w2s[o * 128 + tid] = w2g[(size_t)o * NFF + blockIdx.x * 128 + tid];
        }
        __syncthreads();

        float po[8][4];
#pragma unroll
        for (int i = 0; i < 8; ++i)
#pragma unroll
            for (int o = 0; o < 4; ++o) po[i][o] = 0.f;

#pragma unroll
        for (int mt = 0; mt < 4; ++mt) {
#pragma unroll
            for (int nt = 0; nt < 4; ++nt) {
                const int clb = wn * 32 + (lane & 3) * 2 + nt * 8;
                const float b0 = bias[blockIdx.x * 128 + clb];
                const float b1v = bias[blockIdx.x * 128 + clb + 1];
                float t00 = fmaxf(acc[mt][nt][0] + b0, 0.f);
                float t01 = fmaxf(acc[mt][nt][1] + b1v, 0.f);
                float t10 = fmaxf(acc[mt][nt][2] + b0, 0.f);
                float t11 = fmaxf(acc[mt][nt][3] + b1v, 0.f);
#pragma unroll
                for (int o = 0; o < 4; ++o) {
                    float w0 = w2s[o * 128 + clb], w1w = w2s[o * 128 + clb + 1];
                    po[mt * 2 + 0][o] += t00 * w0 + t01 * w1w;
                    po[mt * 2 + 1][o] += t10 * w0 + t11 * w1w;
                }
            }
        }
#pragma unroll
        for (int off = 1; off <= 2; off <<= 1)
#pragma unroll
            for (int i = 0; i < 8; ++i)
#pragma unroll
                for (int o = 0; o < 4; ++o)
                    po[i][o] += __shfl_xor_sync(0xffffffffu, po[i][o], off);

        if ((lane & 3) == 0) {
            const int rq = lane >> 2;
#pragma unroll
            for (int i = 0; i < 8; ++i) {
                int row = wm * 64 + rq + (i >> 1) * 16 + (i & 1) * 8;
#pragma unroll
                for (int o = 0; o < 4; ++o)
                    red[(wn * 128 + row) * 4 + o] = po[i][o];
            }
        }
        __syncthreads();
        if (tid < 128) {
            float4 s = make_float4(0.f, 0.f, 0.f, 0.f);
#pragma unroll
            for (int w = 0; w < 4; ++w) {
                float4 v = *(float4*)&red[(w * 128 + tid) * 4];
                s.x += v.x; s.y += v.y; s.z += v.z; s.w += v.w;
            }
            *(float4*)(part + ((size_t)(blockIdx.y * 128 + tid) * 16
                               + blockIdx.x) * 4) = s;
        }
        return;
    }

    // ---- standard epilogue -------------------------------------------------
    const int row0 = blockIdx.y * 128 + wm * 64 + (lane >> 2);
    const int col0 = blockIdx.x * 128 + wn * 32 + (lane & 3) * 2;
#pragma unroll
    for (int mt = 0; mt < 4; ++mt) {
#pragma unroll
        for (int nt = 0; nt < 4; ++nt) {
            const int cI = col0 + nt * 8;
            const float b0 = bias[cI], b1 = bias[cI + 1];
            float2 v0, v1;
            v0.x = acc[mt][nt][0] + b0; v0.y = acc[mt][nt][1] + b1;
            v1.x = acc[mt][nt][2] + b0; v1.y = acc[mt][nt][3] + b1;
            const int r = row0 + mt * 16;
            if (STORE_C) {
                *(float2*)(C + (size_t)r * N + cI)       = v0;
                *(float2*)(C + (size_t)(r + 8) * N + cI) = v1;
            }
            if (WSPLITS) {
                __half h0, l0, h1, l1;
                split1(v0.x, h0, l0); split1(v0.y, h1, l1);
                *(__half2*)(Oh + (size_t)r * N + cI) = __halves2half2(h0, h1);
                *(__half2*)(Ol + (size_t)r * N + cI) = __halves2half2(l0, l1);
                split1(v1.x, h0, l0); split1(v1.y, h1, l1);
                *(__half2*)(Oh + (size_t)(r + 8) * N + cI) = __halves2half2(h0, h1);
                *(__half2*)(Ol + (size_t)(r + 8) * N + cI) = __halves2half2(l0, l1);
                float r0x = fmaxf(v0.x, 0.f), r0y = fmaxf(v0.y, 0.f);
                float r1x = fmaxf(v1.x, 0.f), r1y = fmaxf(v1.y, 0.f);
                split1(r0x, h0, l0); split1(r0y, h1, l1);
                *(__half2*)(Rh + (size_t)r * N + cI) = __halves2half2(h0, h1);
                *(__half2*)(Rl + (size_t)r * N + cI) = __halves2half2(l0, l1);
                split1(r1x, h0, l0); split1(r1y, h1, l1);
                *(__half2*)(Rh + (size_t)(r + 8) * N + cI) = __halves2half2(h0, h1);
                *(__half2*)(Rl + (size_t)(r + 8) * N + cI) = __halves2half2(l0, l1);
            }
        }
    }
}

// ---------------- prep: all weight/state splits + xy zero, ONE launch -------
// Weights keep only the hi plane (2-pass everywhere); ptf keeps hi+lo.
__global__ void prep_kernel(const float* __restrict__ whh, const float* __restrict__ wfc,
                            const float* __restrict__ w1f, const float* __restrict__ ptf,
                            __half* __restrict__ whh_h,
                            __half* __restrict__ wfc_h,
                            __half* __restrict__ w1_h,
                            __half* __restrict__ hp_h,  __half* __restrict__ hp_l,
                            float* __restrict__ xy)
{
    const int n0 = 3 * HH * HH;
    const int n1 = n0 + HH * 2 * HH;
    const int n2 = n1 + NFF * HH;
    const int n3 = n2 + NB * HH;
    const int n4 = n3 + NB * NOUT;
    int i = (blockIdx.x * blockDim.x + threadIdx.x) * 4;
    if (i >= n4) return;
    if (i >= n3) {
        *(float4*)(xy + (i - n3)) = make_float4(0.f, 0.f, 0.f, 0.f);
        return;
    }
    if (i >= n2) {
        int off = i - n2;
        float4 v = *(const float4*)(ptf + off);
        __half h0, l0, h1, l1, h2, l2, h3, l3;
        split1(v.x, h0, l0); split1(v.y, h1, l1);
        split1(v.z, h2, l2); split1(v.w, h3, l3);
        *(__half2*)(hp_h + off)     = __halves2half2(h0, h1);
        *(__half2*)(hp_h + off + 2) = __halves2half2(h2, h3);
        *(__half2*)(hp_l + off)     = __halves2half2(l0, l1);
        *(__half2*)(hp_l + off + 2) = __halves2half2(l2, l3);
        return;
    }
    const float* src; __half* hi; int off;
    if (i < n0)      { src = whh; hi = whh_h; off = i; }
    else if (i < n1) { src = wfc; hi = wfc_h; off = i - n0; }
    else             { src = w1f; hi = w1_h;  off = i - n1; }
    float4 v = *(const float4*)(src + off);
    *(__half2*)(hi + off)     = __halves2half2(__float2half_rn(v.x), __float2half_rn(v.y));
    *(__half2*)(hi + off + 2) = __halves2half2(__float2half_rn(v.z), __float2half_rn(v.w));
}

// ---------------- GRU gate fusion (r,z,n order); planes in, planes out ------
__global__ void gru_gates_kernel(const float* __restrict__ gh,
                                 const float* __restrict__ x, int ldx,
                                 const __half* __restrict__ php,  // hprev hi
                                 const __half* __restrict__ plp,  // hprev lo
                                 int ldh,
                                 const float* __restrict__ w_ih,  // [3H,4]
                                 const float* __restrict__ b_ih,  // [3H]
                                 __half* __restrict__ ph,         // out hi plane
                                 __half* __restrict__ pl,         // out lo plane
                                 int ldp)
{
    int j = blockIdx.x * blockDim.x + threadIdx.x;   // 0..H-1
    int b = blockIdx.y;
    float4 xv = *(const float4*)(x + (size_t)b * ldx);

    float ig[3];
#pragma unroll
    for (int g = 0; g < 3; ++g) {
        int rI = g * HH + j;
        float4 w = *(const float4*)(w_ih + (size_t)rI * 4);
        ig[g] = b_ih[rI] + xv.x * w.x + xv.y * w.y + xv.z * w.z + xv.w * w.w;
    }
    const float* ghb = gh + (size_t)b * (3 * HH);
    float gr = ghb[j], gz = ghb[HH + j], gn = ghb[2 * HH + j];
    float r = 1.f / (1.f + expf(-(ig[0] + gr)));
    float z = 1.f / (1.f + expf(-(ig[1] + gz)));
    float n = tanhf(ig[2] + r * gn);
    float hp = __half2float(php[(size_t)b * ldh + j])
             + __half2float(plp[(size_t)b * ldh + j]);
    float h = (1.f - z) * n + z * hp;

    __half hh_, hl_;
    split1(h, hh_, hl_);
    ph[(size_t)b * ldp + j] = hh_;
    pl[(size_t)b * ldp + j] = hl_;
}

// ---------------- finalize: sum partials, update xy, write out --------------
__global__ void finalize_kernel(const float* __restrict__ part,
                                const float* __restrict__ b2,
                                float* __restrict__ xy,
                                float* __restrict__ out, int step)
{
    int b = blockIdx.x * blockDim.x + threadIdx.x;
    if (b >= NB) return;
    const float4* p = (const float4*)(part + (size_t)b * 64);
    float4 s = p[0];
#pragma unroll
    for (int j = 1; j < 16; ++j) {
        float4 v = p[j];
        s.x += v.x; s.y += v.y; s.z += v.z; s.w += v.w;
    }
    float4 cur = *(float4*)(xy + (size_t)b * 4);
    cur.x += s.x + b2[0];
    cur.y += s.y + b2[1];
    cur.z += s.z + b2[2];
    cur.w += s.w + b2[3];
    *(float4*)(xy + (size_t)b * 4) = cur;
    *(float4*)(out + (size_t)b * NHOR * NOUT + step * NOUT) = cur;
}

// ---------------- launch -----------------------------------------------------
extern "C" void kernel_launch(void* const* d_in, const int* in_sizes, int n_in,
                              void* d_out, int out_size)
{
    const float* pv   = (const float*)d_in[0];
    const float* ptf  = (const float*)d_in[1];
    const float* w_ih = (const float*)d_in[2];
    const float* w_hh = (const float*)d_in[3];
    const float* b_ih = (const float*)d_in[4];
    const float* b_hh = (const float*)d_in[5];
    const float* w_fc = (const float*)d_in[6];
    const float* b_fc = (const float*)d_in[7];
    const float* w1   = (const float*)d_in[8];
    const float* b1   = (const float*)d_in[9];
    const float* w2   = (const float*)d_in[10];
    const float* b2   = (const float*)d_in[11];
    float* out = (float*)d_out;

    float *gh, *xy, *part;
    __half *hp_h, *hp_l, *hc_h, *hc_l, *hr_h, *hr_l;
    __half *whh_h, *wfc_h, *w1_h;
    cudaGetSymbolAddress((void**)&gh, g_gh);
    cudaGetSymbolAddress((void**)&xy, g_xy);
    cudaGetSymbolAddress((void**)&part, g_part);
    cudaGetSymbolAddress((void**)&hp_h, g_hp_h);
    cudaGetSymbolAddress((void**)&hp_l, g_hp_l);
    cudaGetSymbolAddress((void**)&hc_h, g_hc_h);
    cudaGetSymbolAddress((void**)&hc_l, g_hc_l);
    cudaGetSymbolAddress((void**)&hr_h, g_hr_h);
    cudaGetSymbolAddress((void**)&hr_l, g_hr_l);
    cudaGetSymbolAddress((void**)&whh_h, g_whh_h);
    cudaGetSymbolAddress((void**)&wfc_h, g_wfc_h);
    cudaGetSymbolAddress((void**)&w1_h, g_w1_h);

    cudaFuncSetAttribute(hgemm<1, 0, 0>, cudaFuncAttributeMaxDynamicSharedMemorySize, SMEM_DYN);
    cudaFuncSetAttribute(hgemm<0, 1, 0>, cudaFuncAttributeMaxDynamicSharedMemorySize, SMEM_DYN);
    cudaFuncSetAttribute(hgemm<0, 0, 1>, cudaFuncAttributeMaxDynamicSharedMemorySize, SMEM_DYN);

    // ---- side stream + per-step fork/join events (host-side handles only;
    // created once, reused deterministically on every call) ----
    static cudaStream_t sS = nullptr;
    static cudaEvent_t evFC[NHOR], evFin[NHOR];
    if (!sS) {
        cudaStreamCreateWithFlags(&sS, cudaStreamNonBlocking);
        for (int i = 0; i < NHOR; ++i) {
            cudaEventCreateWithFlags(&evFC[i], cudaEventDisableTiming);
            cudaEventCreateWithFlags(&evFin[i], cudaEventDisableTiming);
        }
    }

    // ---- prep (single launch): split weights + ptf, zero xy ----
    {
        const int n4 = 3 * HH * HH + HH * 2 * HH + NFF * HH + NB * HH + NB * NOUT;
        prep_kernel<<<(n4 / 4 + 255) / 256, 256>>>(
            w_hh, w_fc, w1, ptf,
            whh_h, wfc_h, w1_h, hp_h, hp_l, xy);
    }

    for (int i = 0; i < NHOR; ++i) {
        // cell 1 GEMM (2-pass): gh = hprev @ w_hh^T + b_hh
        // (depends only on hp planes from fc(i-1); overlaps MLP branch of i-1)
        hgemm<1, 0, 0><<<dim3(3 * HH / 128, NB / 128), 256, SMEM_DYN>>>(
            hp_h, hp_l, HH, whh_h, HH, b_hh, gh, 3 * HH,
            nullptr, nullptr, nullptr, nullptr, nullptr, nullptr);

        // gates1 needs xy -> join with finalize(i-1) on side stream
        if (i > 0) cudaStreamWaitEvent(0, evFin[i - 1], 0);
        gru_gates_kernel<<<dim3(HH / 256, NB), 256>>>(
            gh, xy, NOUT, hp_h, hp_l, HH, w_ih, b_ih,
            hc_h, hc_l, 2 * HH);

        // cell 2 GEMM (2-pass): gh = h1 @ w_hh^T + b_hh
        hgemm<1, 0, 0><<<dim3(3 * HH / 128, NB / 128), 256, SMEM_DYN>>>(
            hc_h, hc_l, 2 * HH, whh_h, HH, b_hh, gh, 3 * HH,
            nullptr, nullptr, nullptr, nullptr, nullptr, nullptr);
        gru_gates_kernel<<<dim3(HH / 256, NB), 256>>>(
            gh, pv + i * NOUT, NHOR * NOUT, hc_h, hc_l, 2 * HH, w_ih, b_ih,
            hc_h + HH, hc_l + HH, 2 * HH);

        // hx = hcat @ w_fc^T + b_fc ; emit hp planes + relu planes (2-pass)
        hgemm<0, 1, 0><<<dim3(HH / 128, NB / 128), 256, SMEM_DYN>>>(
            hc_h, hc_l, 2 * HH, wfc_h, 2 * HH, b_fc, nullptr, HH,
            hp_h, hp_l, hr_h, hr_l, nullptr, nullptr);
        cudaEventRecord(evFC[i], 0);

        // ---- MLP branch on side stream (overlaps next step's cell-1 GEMM) --
        cudaStreamWaitEvent(sS, evFC[i], 0);
        hgemm<0, 0, 1><<<dim3(NFF / 128, NB / 128), 256, SMEM_DYN, sS>>>(
            hr_h, hr_l, HH, w1_h, HH, b1, nullptr, NFF,
            nullptr, nullptr, nullptr, nullptr, w2, part);
        finalize_kernel<<<(NB + 255) / 256, 256, 0, sS>>>(part, b2, xy, out, i);
        cudaEventRecord(evFin[i], sS);
    }
    // join the last MLP branch back into the capture stream
    cudaStreamWaitEvent(0, evFin[NHOR - 1], 0);
}

// round 15
// speedup vs baseline: 1.5538x; 1.1819x over previous
#include <cuda_runtime.h>
#include <cuda_fp16.h>
#include <math.h>
#include <stdint.h>

#define NB   16384
#define HH   512
#define NOUT 4
#define NFF  2048
#define NHOR 5

// ---------------- fp32 scratch ----------------------------------------------
__device__ float g_gh[(size_t)NB * 3 * HH];       // gate pre-activations [B,3H]
__device__ float g_xy[(size_t)NB * NOUT];         // running xy
__device__ float g_part[(size_t)NB * 16 * NOUT];  // mlp partials [B,16,4]

// ---------------- fp16 hi/lo planes (GEMM operands) -------------------------
__device__ __align__(16) __half g_hp_h[(size_t)NB * HH];      // hprev (hx)
__device__ __align__(16) __half g_hp_l[(size_t)NB * HH];
__device__ __align__(16) __half g_hc_h[(size_t)NB * 2 * HH];  // hcat [h1|h2]
__device__ __align__(16) __half g_hc_l[(size_t)NB * 2 * HH];
__device__ __align__(16) __half g_hr_h[(size_t)NB * HH];      // relu(hx)
__device__ __align__(16) __half g_hr_l[(size_t)NB * HH];
__device__ __align__(16) __half g_whh_h[3 * HH * HH];
__device__ __align__(16) __half g_wfc_h[HH * 2 * HH];
__device__ __align__(16) __half g_w1_h[NFF * HH];

// ---------------- helpers ---------------------------------------------------
__device__ __forceinline__ uint32_t smem_u32(const void* p) {
    uint32_t a;
    asm("{ .reg .u64 t; cvta.to.shared.u64 t, %1; cvt.u32.u64 %0, t; }"
        : "=r"(a) : "l"(p));
    return a;
}
__device__ __forceinline__ void split1(float x, __half& h, __half& l) {
    h = __float2half_rn(x);
    l = __float2half_rn(x - __half2float(h));
}
__device__ __forceinline__ void ldsm4(uint32_t& r0, uint32_t& r1,
                                      uint32_t& r2, uint32_t& r3, uint32_t addr) {
    asm volatile("ldmatrix.sync.aligned.m8n8.x4.shared.b16 {%0,%1,%2,%3}, [%4];"
                 : "=r"(r0), "=r"(r1), "=r"(r2), "=r"(r3) : "r"(addr));
}
__device__ __forceinline__ void hmma(float* d, const uint32_t* a,
                                     uint32_t b0, uint32_t b1) {
    asm volatile(
        "mma.sync.aligned.m16n8k16.row.col.f32.f16.f16.f32 "
        "{%0,%1,%2,%3}, {%4,%5,%6,%7}, {%8,%9}, {%0,%1,%2,%3};"
        : "+f"(d[0]), "+f"(d[1]), "+f"(d[2]), "+f"(d[3])
        : "r"(a[0]), "r"(a[1]), "r"(a[2]), "r"(a[3]), "r"(b0), "r"(b1));
}
__device__ __forceinline__ void cpasync16(uint32_t dst, const void* src) {
    asm volatile("cp.async.cg.shared.global [%0], [%1], 16;" :: "r"(dst), "l"(src));
}

// smem plane: 128 rows x 64 fp16 = 128B/row (BK=64). Swizzle: 16B-unit u within
// a row is stored at u ^ (row & 7) -> conflict-free for cp.async stores and
// ldmatrix reads. 2-stage double buffer.
#define STAGES  2
#define PL      16384           // one plane: 128*128B
// planes/stage: ALO ? 3 (Ah, Al, Wh) : 2 (Ah, Wh)
#define SMEM_MAX (STAGES * 3 * PL)   // 96 KB

// =====================  split-fp16 HMMA GEMM, BK=64 double-buffer  ==========
// C[B,N] = A @ W^T + bias; A as fp16 hi(/lo) planes, W truncated hi plane.
// ALO=1: (A_hi + A_lo) * W_hi (exact A). ALO=0: A_hi * W_hi (~2^-12 on A too).
// STORE_C: write fp32 C. WSPLITS: write hi/lo planes of C and relu(C).
// FUSED: no store; reduce relu(tile) against w2 into partials [B,16,4].
template <int STORE_C, int WSPLITS, int ALO, int FUSED>
__global__ __launch_bounds__(256, 2)
void hgemm(const __half* __restrict__ Ah, const __half* __restrict__ Al, int lda,
           const __half* __restrict__ Wh, int K,
           const float* __restrict__ bias, float* __restrict__ C, int N,
           __half* __restrict__ Oh, __half* __restrict__ Ol,
           __half* __restrict__ Rh, __half* __restrict__ Rl,
           const float* __restrict__ w2g, float* __restrict__ part)
{
    extern __shared__ char dsm[];
    const uint32_t sb = smem_u32(dsm);
    const int NPL = ALO ? 3 : 2;          // planes per stage
    const uint32_t STG = (uint32_t)NPL * PL;
    const uint32_t WOFF = ALO ? 2u * PL : 1u * PL;

    const int tid  = threadIdx.x;
    const int wid  = tid >> 5;
    const int lane = tid & 31;
    const int wm   = wid & 1;
    const int wn   = wid >> 1;
    const int grp  = lane >> 3;
    const int wi   = lane & 7;

    const __half* Abh = Ah + (size_t)blockIdx.y * 128 * lda;
    const __half* Abl = ALO ? (Al + (size_t)blockIdx.y * 128 * lda) : Abh;
    const __half* Wbh = Wh + (size_t)blockIdx.x * 128 * K;

    const int rowA0 = wm * 64 + (grp & 1) * 8 + wi;
    const int cA    = grp >> 1;
    const int rowW0 = wn * 32 + (grp >> 1) * 8 + wi;
    const int cW    = grp & 1;

    float acc[4][4][4];
#pragma unroll
    for (int mt = 0; mt < 4; ++mt)
#pragma unroll
        for (int nt = 0; nt < 4; ++nt)
#pragma unroll
            for (int r = 0; r < 4; ++r) acc[mt][nt][r] = 0.f;

    const int nchunk = K >> 6;   // K / 64

    // copy: 1024 16B-units per plane; 256 threads x 4 iters
#define ISSUE(c) do {                                                          \
    int k0_ = (c) << 6;                                                        \
    uint32_t stg_ = sb + (uint32_t)((c) & 1) * STG;                            \
    _Pragma("unroll")                                                          \
    for (int it_ = 0; it_ < 4; ++it_) {                                        \
        int id_ = tid + 256 * it_;                                             \
        int row_ = id_ >> 3, u_ = id_ & 7;                                     \
        uint32_t d_ = stg_ + (uint32_t)row_ * 128                              \
                    + (uint32_t)((u_ ^ (row_ & 7)) << 4);                      \
        cpasync16(d_,        Abh + (size_t)row_ * lda + k0_ + u_ * 8);         \
        if (ALO)                                                               \
            cpasync16(d_ + PL, Abl + (size_t)row_ * lda + k0_ + u_ * 8);       \
        cpasync16(d_ + WOFF, Wbh + (size_t)row_ * K  + k0_ + u_ * 8);          \
    }                                                                          \
} while (0)

    ISSUE(0);
    asm volatile("cp.async.commit_group;");

    for (int c = 0; c < nchunk; ++c) {
        asm volatile("cp.async.wait_group 0;");
        __syncthreads();
        if (c + 1 < nchunk) {
            ISSUE(c + 1);
            asm volatile("cp.async.commit_group;");
        }

        const uint32_t stg = sb + (uint32_t)(c & 1) * STG;
#pragma unroll
        for (int ks = 0; ks < 4; ++ks) {
            uint32_t bh[4][2];
#pragma unroll
            for (int nh = 0; nh < 2; ++nh) {
                int row = rowW0 + nh * 16;
                uint32_t wd = stg + WOFF + (uint32_t)row * 128
                            + (uint32_t)(((ks * 2 + cW) ^ (row & 7)) << 4);
                uint32_t r0, r1, r2, r3;
                ldsm4(r0, r1, r2, r3, wd);
                bh[nh * 2 + 0][0] = r0; bh[nh * 2 + 0][1] = r1;
                bh[nh * 2 + 1][0] = r2; bh[nh * 2 + 1][1] = r3;
            }
            uint32_t a[4][4];
#pragma unroll
            for (int mt = 0; mt < 4; ++mt) {
                int row = rowA0 + mt * 16;
                uint32_t ad = stg + (uint32_t)row * 128
                            + (uint32_t)(((ks * 2 + cA) ^ (row & 7)) << 4);
                ldsm4(a[mt][0], a[mt][1], a[mt][2], a[mt][3], ad);
#pragma unroll
                for (int nt = 0; nt < 4; ++nt)
                    hmma(acc[mt][nt], a[mt], bh[nt][0], bh[nt][1]);
            }
            if (ALO) {
#pragma unroll
                for (int mt = 0; mt < 4; ++mt) {
                    int row = rowA0 + mt * 16;
                    uint32_t ad = stg + PL + (uint32_t)row * 128
                                + (uint32_t)(((ks * 2 + cA) ^ (row & 7)) << 4);
                    ldsm4(a[mt][0], a[mt][1], a[mt][2], a[mt][3], ad);
#pragma unroll
                    for (int nt = 0; nt < 4; ++nt)
                        hmma(acc[mt][nt], a[mt], bh[nt][0], bh[nt][1]);
                }
            }
        }
    }
#undef ISSUE

    if (FUSED) {
        // ---- fused mlp2: relu(tile) . w2 -> partials [B, 16, 4] ------------
        __syncthreads();                       // pipeline smem now reusable
        float* w2s = (float*)dsm;              // [4][128]
        float* red = (float*)(dsm + 2048);     // [4 warps-n][128 rows][4 outs]
        if (tid < 128) {
#pragma unroll
            for (int o = 0; o < 4; ++o)
                w2s[o * 128 + tid] = w2g[(size_t)o * NFF + blockIdx.x * 128 + tid];
        }
        __syncthreads();

        float po[8][4];
#pragma unroll
        for (int i = 0; i < 8; ++i)
#pragma unroll
            for (int o = 0; o < 4; ++o) po[i][o] = 0.f;

#pragma unroll
        for (int mt = 0; mt < 4; ++mt) {
#pragma unroll
            for (int nt = 0; nt < 4; ++nt) {
                const int clb = wn * 32 + (lane & 3) * 2 + nt * 8;
                const float b0 = bias[blockIdx.x * 128 + clb];
                const float b1v = bias[blockIdx.x * 128 + clb + 1];
                float t00 = fmaxf(acc[mt][nt][0] + b0, 0.f);
                float t01 = fmaxf(acc[mt][nt][1] + b1v, 0.f);
                float t10 = fmaxf(acc[mt][nt][2] + b0, 0.f);
                float t11 = fmaxf(acc[mt][nt][3] + b1v, 0.f);
#pragma unroll
                for (int o = 0; o < 4; ++o) {
                    float w0 = w2s[o * 128 + clb], w1w = w2s[o * 128 + clb + 1];
                    po[mt * 2 + 0][o] += t00 * w0 + t01 * w1w;
                    po[mt * 2 + 1][o] += t10 * w0 + t11 * w1w;
                }
            }
        }
#pragma unroll
        for (int off = 1; off <= 2; off <<= 1)
#pragma unroll
            for (int i = 0; i < 8; ++i)
#pragma unroll
                for (int o = 0; o < 4; ++o)
                    po[i][o] += __shfl_xor_sync(0xffffffffu, po[i][o], off);

        if ((lane & 3) == 0) {
            const int rq = lane >> 2;
#pragma unroll
            for (int i = 0; i < 8; ++i) {
                int row = wm * 64 + rq + (i >> 1) * 16 + (i & 1) * 8;
#pragma unroll
                for (int o = 0; o < 4; ++o)
                    red[(wn * 128 + row) * 4 + o] = po[i][o];
            }
        }
        __syncthreads();
        if (tid < 128) {
            float4 s = make_float4(0.f, 0.f, 0.f, 0.f);
#pragma unroll
            for (int w = 0; w < 4; ++w) {
                float4 v = *(float4*)&red[(w * 128 + tid) * 4];
                s.x += v.x; s.y += v.y; s.z += v.z; s.w += v.w;
            }
            *(float4*)(part + ((size_t)(blockIdx.y * 128 + tid) * 16
                               + blockIdx.x) * 4) = s;
        }
        return;
    }

    // ---- standard epilogue -------------------------------------------------
    const int row0 = blockIdx.y * 128 + wm * 64 + (lane >> 2);
    const int col0 = blockIdx.x * 128 + wn * 32 + (lane & 3) * 2;
#pragma unroll
    for (int mt = 0; mt < 4; ++mt) {
#pragma unroll
        for (int nt = 0; nt < 4; ++nt) {
            const int cI = col0 + nt * 8;
            const float b0 = bias[cI], b1 = bias[cI + 1];
            float2 v0, v1;
            v0.x = acc[mt][nt][0] + b0; v0.y = acc[mt][nt][1] + b1;
            v1.x = acc[mt][nt][2] + b0; v1.y = acc[mt][nt][3] + b1;
            const int r = row0 + mt * 16;
            if (STORE_C) {
                *(float2*)(C + (size_t)r * N + cI)       = v0;
                *(float2*)(C + (size_t)(r + 8) * N + cI) = v1;
            }
            if (WSPLITS) {
                __half h0, l0, h1, l1;
                split1(v0.x, h0, l0); split1(v0.y, h1, l1);
                *(__half2*)(Oh + (size_t)r * N + cI) = __halves2half2(h0, h1);
                *(__half2*)(Ol + (size_t)r * N + cI) = __halves2half2(l0, l1);
                split1(v1.x, h0, l0); split1(v1.y, h1, l1);
                *(__half2*)(Oh + (size_t)(r + 8) * N + cI) = __halves2half2(h0, h1);
                *(__half2*)(Ol + (size_t)(r + 8) * N + cI) = __halves2half2(l0, l1);
                float r0x = fmaxf(v0.x, 0.f), r0y = fmaxf(v0.y, 0.f);
                float r1x = fmaxf(v1.x, 0.f), r1y = fmaxf(v1.y, 0.f);
                split1(r0x, h0, l0); split1(r0y, h1, l1);
                *(__half2*)(Rh + (size_t)r * N + cI) = __halves2half2(h0, h1);
                *(__half2*)(Rl + (size_t)r * N + cI) = __halves2half2(l0, l1);
                split1(r1x, h0, l0); split1(r1y, h1, l1);
                *(__half2*)(Rh + (size_t)(r + 8) * N + cI) = __halves2half2(h0, h1);
                *(__half2*)(Rl + (size_t)(r + 8) * N + cI) = __halves2half2(l0, l1);
            }
        }
    }
}

// ---------------- prep: all weight/state splits + xy zero, ONE launch -------
// Weights keep only the hi plane (2-pass everywhere); ptf keeps hi+lo.
__global__ void prep_kernel(const float* __restrict__ whh, const float* __restrict__ wfc,
                            const float* __restrict__ w1f, const float* __restrict__ ptf,
                            __half* __restrict__ whh_h,
                            __half* __restrict__ wfc_h,
                            __half* __restrict__ w1_h,
                            __half* __restrict__ hp_h,  __half* __restrict__ hp_l,
                            float* __restrict__ xy)
{
    const int n0 = 3 * HH * HH;
    const int n1 = n0 + HH * 2 * HH;
    const int n2 = n1 + NFF * HH;
    const int n3 = n2 + NB * HH;
    const int n4 = n3 + NB * NOUT;
    int i = (blockIdx.x * blockDim.x + threadIdx.x) * 4;
    if (i >= n4) return;
    if (i >= n3) {
        *(float4*)(xy + (i - n3)) = make_float4(0.f, 0.f, 0.f, 0.f);
        return;
    }
    if (i >= n2) {
        int off = i - n2;
        float4 v = *(const float4*)(ptf + off);
        __half h0, l0, h1, l1, h2, l2, h3, l3;
        split1(v.x, h0, l0); split1(v.y, h1, l1);
        split1(v.z, h2, l2); split1(v.w, h3, l3);
        *(__half2*)(hp_h + off)     = __halves2half2(h0, h1);
        *(__half2*)(hp_h + off + 2) = __halves2half2(h2, h3);
        *(__half2*)(hp_l + off)     = __halves2half2(l0, l1);
        *(__half2*)(hp_l + off + 2) = __halves2half2(l2, l3);
        return;
    }
    const float* src; __half* hi; int off;
    if (i < n0)      { src = whh; hi = whh_h; off = i; }
    else if (i < n1) { src = wfc; hi = wfc_h; off = i - n0; }
    else             { src = w1f; hi = w1_h;  off = i - n1; }
    float4 v = *(const float4*)(src + off);
    *(__half2*)(hi + off)     = __halves2half2(__float2half_rn(v.x), __float2half_rn(v.y));
    *(__half2*)(hi + off + 2) = __halves2half2(__float2half_rn(v.z), __float2half_rn(v.w));
}

// ---------------- GRU gate fusion (r,z,n order); planes in, planes out ------
__global__ void gru_gates_kernel(const float* __restrict__ gh,
                                 const float* __restrict__ x, int ldx,
                                 const __half* __restrict__ php,  // hprev hi
                                 const __half* __restrict__ plp,  // hprev lo
                                 int ldh,
                                 const float* __restrict__ w_ih,  // [3H,4]
                                 const float* __restrict__ b_ih,  // [3H]
                                 __half* __restrict__ ph,         // out hi plane
                                 __half* __restrict__ pl,         // out lo plane
                                 int ldp)
{
    int j = blockIdx.x * blockDim.x + threadIdx.x;   // 0..H-1
    int b = blockIdx.y;
    float4 xv = *(const float4*)(x + (size_t)b * ldx);

    float ig[3];
#pragma unroll
    for (int g = 0; g < 3; ++g) {
        int rI = g * HH + j;
        float4 w = *(const float4*)(w_ih + (size_t)rI * 4);
        ig[g] = b_ih[rI] + xv.x * w.x + xv.y * w.y + xv.z * w.z + xv.w * w.w;
    }
    const float* ghb = gh + (size_t)b * (3 * HH);
    float gr = ghb[j], gz = ghb[HH + j], gn = ghb[2 * HH + j];
    float r = 1.f / (1.f + expf(-(ig[0] + gr)));
    float z = 1.f / (1.f + expf(-(ig[1] + gz)));
    float n = tanhf(ig[2] + r * gn);
    float hp = __half2float(php[(size_t)b * ldh + j])
             + __half2float(plp[(size_t)b * ldh + j]);
    float h = (1.f - z) * n + z * hp;

    __half hh_, hl_;
    split1(h, hh_, hl_);
    ph[(size_t)b * ldp + j] = hh_;
    pl[(size_t)b * ldp + j] = hl_;
}

// ---------------- finalize: sum partials, update xy, write out --------------
__global__ void finalize_kernel(const float* __restrict__ part,
                                const float* __restrict__ b2,
                                float* __restrict__ xy,
                                float* __restrict__ out, int step)
{
    int b = blockIdx.x * blockDim.x + threadIdx.x;
    if (b >= NB) return;
    const float4* p = (const float4*)(part + (size_t)b * 64);
    float4 s = p[0];
#pragma unroll
    for (int j = 1; j < 16; ++j) {
        float4 v = p[j];
        s.x += v.x; s.y += v.y; s.z += v.z; s.w += v.w;
    }
    float4 cur = *(float4*)(xy + (size_t)b * 4);
    cur.x += s.x + b2[0];
    cur.y += s.y + b2[1];
    cur.z += s.z + b2[2];
    cur.w += s.w + b2[3];
    *(float4*)(xy + (size_t)b * 4) = cur;
    *(float4*)(out + (size_t)b * NHOR * NOUT + step * NOUT) = cur;
}

// ---------------- launch -----------------------------------------------------
extern "C" void kernel_launch(void* const* d_in, const int* in_sizes, int n_in,
                              void* d_out, int out_size)
{
    const float* pv   = (const float*)d_in[0];
    const float* ptf  = (const float*)d_in[1];
    const float* w_ih = (const float*)d_in[2];
    const float* w_hh = (const float*)d_in[3];
    const float* b_ih = (const float*)d_in[4];
    const float* b_hh = (const float*)d_in[5];
    const float* w_fc = (const float*)d_in[6];
    const float* b_fc = (const float*)d_in[7];
    const float* w1   = (const float*)d_in[8];
    const float* b1   = (const float*)d_in[9];
    const float* w2   = (const float*)d_in[10];
    const float* b2   = (const float*)d_in[11];
    float* out = (float*)d_out;

    float *gh, *xy, *part;
    __half *hp_h, *hp_l, *hc_h, *hc_l, *hr_h, *hr_l;
    __half *whh_h, *wfc_h, *w1_h;
    cudaGetSymbolAddress((void**)&gh, g_gh);
    cudaGetSymbolAddress((void**)&xy, g_xy);
    cudaGetSymbolAddress((void**)&part, g_part);
    cudaGetSymbolAddress((void**)&hp_h, g_hp_h);
    cudaGetSymbolAddress((void**)&hp_l, g_hp_l);
    cudaGetSymbolAddress((void**)&hc_h, g_hc_h);
    cudaGetSymbolAddress((void**)&hc_l, g_hc_l);
    cudaGetSymbolAddress((void**)&hr_h, g_hr_h);
    cudaGetSymbolAddress((void**)&hr_l, g_hr_l);
    cudaGetSymbolAddress((void**)&whh_h, g_whh_h);
    cudaGetSymbolAddress((void**)&wfc_h, g_wfc_h);
    cudaGetSymbolAddress((void**)&w1_h, g_w1_h);

    cudaFuncSetAttribute(hgemm<1, 0, 1, 0>, cudaFuncAttributeMaxDynamicSharedMemorySize, SMEM_MAX);
    cudaFuncSetAttribute(hgemm<0, 1, 1, 0>, cudaFuncAttributeMaxDynamicSharedMemorySize, SMEM_MAX);
    cudaFuncSetAttribute(hgemm<0, 0, 0, 1>, cudaFuncAttributeMaxDynamicSharedMemorySize, SMEM_MAX);

    // ---- side stream + per-step fork/join events (host-side handles only;
    // created once, reused deterministically on every call) ----
    static cudaStream_t sS = nullptr;
    static cudaEvent_t evFC[NHOR], evFin[NHOR];
    if (!sS) {
        cudaStreamCreateWithFlags(&sS, cudaStreamNonBlocking);
        for (int i = 0; i < NHOR; ++i) {
            cudaEventCreateWithFlags(&evFC[i], cudaEventDisableTiming);
            cudaEventCreateWithFlags(&evFin[i], cudaEventDisableTiming);
        }
    }

    // ---- prep (single launch): split weights + ptf, zero xy ----
    {
        const int n4 = 3 * HH * HH + HH * 2 * HH + NFF * HH + NB * HH + NB * NOUT;
        prep_kernel<<<(n4 / 4 + 255) / 256, 256>>>(
            w_hh, w_fc, w1, ptf,
            whh_h, wfc_h, w1_h, hp_h, hp_l, xy);
    }

    const int SM3 = STAGES * 3 * PL;   // 96 KB (ALO variants)
    const int SM2 = STAGES * 2 * PL;   // 64 KB (FUSED 1-pass)

    for (int i = 0; i < NHOR; ++i) {
        // cell 1 GEMM (2-pass): gh = hprev @ w_hh^T + b_hh
        // (depends only on hp planes from fc(i-1); overlaps MLP branch of i-1)
        hgemm<1, 0, 1, 0><<<dim3(3 * HH / 128, NB / 128), 256, SM3>>>(
            hp_h, hp_l, HH, whh_h, HH, b_hh, gh, 3 * HH,
            nullptr, nullptr, nullptr, nullptr, nullptr, nullptr);

        // gates1 needs xy -> join with finalize(i-1) on side stream
        if (i > 0) cudaStreamWaitEvent(0, evFin[i - 1], 0);
        gru_gates_kernel<<<dim3(HH / 256, NB), 256>>>(
            gh, xy, NOUT, hp_h, hp_l, HH, w_ih, b_ih,
            hc_h, hc_l, 2 * HH);

        // cell 2 GEMM (2-pass): gh = h1 @ w_hh^T + b_hh
        hgemm<1, 0, 1, 0><<<dim3(3 * HH / 128, NB / 128), 256, SM3>>>(
            hc_h, hc_l, 2 * HH, whh_h, HH, b_hh, gh, 3 * HH,
            nullptr, nullptr, nullptr, nullptr, nullptr, nullptr);
        gru_gates_kernel<<<dim3(HH / 256, NB), 256>>>(
            gh, pv + i * NOUT, NHOR * NOUT, hc_h, hc_l, 2 * HH, w_ih, b_ih,
            hc_h + HH, hc_l + HH, 2 * HH);

        // hx = hcat @ w_fc^T + b_fc ; emit hp planes + relu planes (2-pass)
        hgemm<0, 1, 1, 0><<<dim3(HH / 128, NB / 128), 256, SM3>>>(
            hc_h, hc_l, 2 * HH, wfc_h, 2 * HH, b_fc, nullptr, HH,
            hp_h, hp_l, hr_h, hr_l, nullptr, nullptr);
        cudaEventRecord(evFC[i], 0);

        // ---- MLP branch on side stream (overlaps next step's cell-1 GEMM) --
        // 1-pass (A_hi * W_hi): additive output path only.
        cudaStreamWaitEvent(sS, evFC[i], 0);
        hgemm<0, 0, 0, 1><<<dim3(NFF / 128, NB / 128), 256, SM2, sS>>>(
            hr_h, nullptr, HH, w1_h, HH, b1, nullptr, NFF,
            nullptr, nullptr, nullptr, nullptr, w2, part);
        finalize_kernel<<<(NB + 255) / 256, 256, 0, sS>>>(part, b2, xy, out, i);
        cudaEventRecord(evFin[i], sS);
    }
    // join the last MLP branch back into the capture stream
    cudaStreamWaitEvent(0, evFin[NHOR - 1], 0);
}